// round 1
// baseline (speedup 1.0000x reference)
#include <cuda_runtime.h>

// ============================================================================
// DPSR: trilinear scatter -> 3D FFT -> spectral Poisson -> iFFT -> gather/norm
// res = 128, sigma = 2, eps = 1e-6, B = 1, N = 250000, F = 3
// ============================================================================

#define RESN 128
#define M3   2097152          // 128^3
#define FPI  3.14159265358979f

// ---- scratch (device globals; no allocation allowed) ----
__device__ float  g_vr[3 * M3];     // scattered real fields (24 MB)
__device__ float2 g_Vc[3 * M3];     // complex spectra of fields (48 MB)
__device__ float2 g_C[M3];          // chi_tilde (16 MB)
__device__ float  g_chi[M3];        // chi_prime (8 MB)
__device__ double g_stats[4];       // [0]=sum(chi_c), [1]=mean, [2]=scale

// ---- complex helpers ----
__device__ __forceinline__ float2 cadd(float2 a, float2 b){ return make_float2(a.x+b.x, a.y+b.y); }
__device__ __forceinline__ float2 csub(float2 a, float2 b){ return make_float2(a.x-b.x, a.y-b.y); }
__device__ __forceinline__ float2 cmul(float2 a, float2 b){
    return make_float2(a.x*b.x - a.y*b.y, a.x*b.y + a.y*b.x);
}
// exp(dir * i * pi * j * invs)
__device__ __forceinline__ float2 twf(float j, float invs, float dir){
    float s, c;
    __sincosf(dir * FPI * j * invs, &s, &c);
    return make_float2(c, s);
}

// ============================================================================
// 128-point radix-2 DIF FFT over tile[pos][line], 16 lines per block,
// 128 threads: t = tid>>4 in [0,8), line = tid&15.
// Each thread owns positions p = t + 8m (m=0..15) for first 4 stages
// (strides 64/32/16/8 all intra-thread), then exchanges to own two
// contiguous 8-blocks for strides 4/2/1, then writes bit-reversed.
// DIR = -1 forward (e^{-i}), +1 inverse (unnormalized).
// ============================================================================
template<int DIR>
__device__ __forceinline__ void fft128_tile(float2 (*tile)[17]){
    const int tid = threadIdx.x;
    const int t   = tid >> 4;      // 0..7  : sub-lane within line
    const int ln  = tid & 15;      // 0..15 : line
    const float dir = (float)DIR;

    float2 v[16];
    #pragma unroll
    for (int m = 0; m < 16; m++) v[m] = tile[t + 8*m][ln];

    // stage s=64 : pairs (m, m+8), twiddle j = p = t+8m
    #pragma unroll
    for (int m = 0; m < 8; m++){
        float2 a = v[m], b = v[m+8];
        v[m]   = cadd(a, b);
        v[m+8] = cmul(csub(a, b), twf((float)(t + 8*m), 1.0f/64.0f, dir));
    }
    // stage s=32 : j = t + 8*(m&3)
    #pragma unroll
    for (int h = 0; h < 16; h += 8)
    #pragma unroll
    for (int m2 = 0; m2 < 4; m2++){
        int m = h + m2;
        float2 a = v[m], b = v[m+4];
        v[m]   = cadd(a, b);
        v[m+4] = cmul(csub(a, b), twf((float)(t + 8*m2), 1.0f/32.0f, dir));
    }
    // stage s=16 : j = t + 8*(m&1)
    #pragma unroll
    for (int h = 0; h < 16; h += 4)
    #pragma unroll
    for (int m2 = 0; m2 < 2; m2++){
        int m = h + m2;
        float2 a = v[m], b = v[m+2];
        v[m]   = cadd(a, b);
        v[m+2] = cmul(csub(a, b), twf((float)(t + 8*m2), 1.0f/16.0f, dir));
    }
    // stage s=8 : j = t (same twiddle for all pairs in thread)
    {
        float2 w8 = twf((float)t, 1.0f/8.0f, dir);
        #pragma unroll
        for (int h = 0; h < 16; h += 2){
            float2 a = v[h], b = v[h+1];
            v[h]   = cadd(a, b);
            v[h+1] = cmul(csub(a, b), w8);
        }
    }

    // exchange: positions are unchanged (in-place DIF); re-own as two
    // contiguous 8-blocks starting at 16t.
    #pragma unroll
    for (int m = 0; m < 16; m++) tile[t + 8*m][ln] = v[m];
    __syncthreads();
    #pragma unroll
    for (int r = 0; r < 16; r++) v[r] = tile[16*t + r][ln];

    // stage s=4 : per 8-block, pairs (r, r+4), j = r
    #pragma unroll
    for (int r0 = 0; r0 < 16; r0 += 8)
    #pragma unroll
    for (int r = 0; r < 4; r++){
        float2 a = v[r0+r], b = v[r0+r+4];
        v[r0+r]   = cadd(a, b);
        v[r0+r+4] = cmul(csub(a, b), twf((float)r, 0.25f, dir));
    }
    // stage s=2 : j in {0,1}; W(1,1/2) = (0, dir)
    {
        const float2 wi = make_float2(0.0f, dir);
        #pragma unroll
        for (int r0 = 0; r0 < 16; r0 += 4){
            float2 a = v[r0],   b = v[r0+2];
            v[r0]   = cadd(a, b);
            v[r0+2] = csub(a, b);
            a = v[r0+1]; b = v[r0+3];
            v[r0+1] = cadd(a, b);
            v[r0+3] = cmul(csub(a, b), wi);
        }
    }
    // stage s=1 : trivial
    #pragma unroll
    for (int r0 = 0; r0 < 16; r0 += 2){
        float2 a = v[r0], b = v[r0+1];
        v[r0]   = cadd(a, b);
        v[r0+1] = csub(a, b);
    }

    __syncthreads();   // all exchange-reads done before bitrev writes
    // output at position p = 16t + r belongs to k = bitrev7(p)
    //   = rev4(r)*8 + rev3(t)
    const int rev3t = ((t & 1) << 2) | (t & 2) | ((t & 4) >> 2);
    #pragma unroll
    for (int r = 0; r < 16; r++){
        int rr = ((r & 1) << 3) | ((r & 2) << 1) | ((r & 4) >> 1) | ((r & 8) >> 3);
        tile[8*rr + rev3t][ln] = v[r];
    }
    __syncthreads();
}

// ============================================================================
// FFT kernels
// ============================================================================

// z-axis forward, real -> complex. blockIdx.x in [0,1024): 16 contiguous lines.
// blockIdx.z = field.
__global__ void __launch_bounds__(128) k_fft_z_r2c(){
    __shared__ float2 tile[128][17];
    const int base = blockIdx.x * 2048 + blockIdx.z * M3;
    for (int i = threadIdx.x; i < 2048; i += 128)
        tile[i & 127][i >> 7] = make_float2(g_vr[base + i], 0.0f);
    __syncthreads();
    fft128_tile<-1>(tile);
    for (int i = threadIdx.x; i < 2048; i += 128)
        g_Vc[base + i] = tile[i & 127][i >> 7];
}

// z-axis inverse, complex -> real part (with 1/128^3 scaling).
__global__ void __launch_bounds__(128) k_fft_z_c2r(){
    __shared__ float2 tile[128][17];
    const int base = blockIdx.x * 2048;
    for (int i = threadIdx.x; i < 2048; i += 128)
        tile[i & 127][i >> 7] = g_C[base + i];
    __syncthreads();
    fft128_tile<1>(tile);
    const float sc = 1.0f / 2097152.0f;
    for (int i = threadIdx.x; i < 2048; i += 128)
        g_chi[base + i] = tile[i & 127][i >> 7].x * sc;
}

// strided axis (y: bstride=16384, estride=128; x: bstride=128, estride=16384)
// blockIdx.x = z-tile (16 consecutive z), blockIdx.y = fixed other index,
// blockIdx.z = field (WHICH==0: g_Vc) or 0 (WHICH==1: g_C). In-place.
template<int DIR, int WHICH>
__global__ void __launch_bounds__(128) k_fft_strided(int bstride, int estride){
    __shared__ float2 tile[128][17];
    float2* g = (WHICH == 0) ? (g_Vc + blockIdx.z * M3) : g_C;
    const int base = blockIdx.y * bstride + blockIdx.x * 16;
    for (int i = threadIdx.x; i < 2048; i += 128){
        int e = i >> 4, d = i & 15;
        tile[e][d] = g[base + e * estride + d];
    }
    __syncthreads();
    fft128_tile<DIR>(tile);
    for (int i = threadIdx.x; i < 2048; i += 128){
        int e = i >> 4, d = i & 15;
        g[base + e * estride + d] = tile[e][d];
    }
}

// ============================================================================
// Pipeline kernels
// ============================================================================

__global__ void k_zero(){
    int i = blockIdx.x * 1024 + threadIdx.x;
    if (i < 3 * M3) g_vr[i] = 0.0f;
    if (i < 4)      g_stats[i] = 0.0;
}

// trilinear corner setup shared by scatter/gather
__device__ __forceinline__ void corners(float px, float py, float pz,
                                        int ix[2], int iy[2], int iz[2],
                                        float wx[2], float wy[2], float wz[2]){
    float prx = px * 128.0f, pry = py * 128.0f, prz = pz * 128.0f;
    float lox = floorf(prx), loy = floorf(pry), loz = floorf(prz);
    ix[0] = ((int)lox) & 127;  iy[0] = ((int)loy) & 127;  iz[0] = ((int)loz) & 127;
    ix[1] = ((int)ceilf(prx)) & 127;
    iy[1] = ((int)ceilf(pry)) & 127;
    iz[1] = ((int)ceilf(prz)) & 127;
    float fx = prx - lox, fy = pry - loy, fz = prz - loz;
    wx[0] = 1.0f - fx; wx[1] = fx;
    wy[0] = 1.0f - fy; wy[1] = fy;
    wz[0] = 1.0f - fz; wz[1] = fz;
}

__global__ void k_scatter(const float* __restrict__ pts,
                          const float* __restrict__ nrm, int N){
    int n = blockIdx.x * 256 + threadIdx.x;
    if (n >= N) return;
    float px = pts[3*n], py = pts[3*n+1], pz = pts[3*n+2];
    float nx = nrm[3*n], ny = nrm[3*n+1], nz = nrm[3*n+2];
    int ix[2], iy[2], iz[2]; float wx[2], wy[2], wz[2];
    corners(px, py, pz, ix, iy, iz, wx, wy, wz);
    #pragma unroll
    for (int c = 0; c < 8; c++){
        int a = (c >> 2) & 1, b = (c >> 1) & 1, d = c & 1;
        float w = wx[a] * wy[b] * wz[d];
        int idx = (ix[a] << 14) | (iy[b] << 7) | iz[d];
        atomicAdd(&g_vr[idx],          w * nx);
        atomicAdd(&g_vr[idx + M3],     w * ny);
        atomicAdd(&g_vr[idx + 2*M3],   w * nz);
    }
}

// chi_tilde = g(k) * (-i/(2pi)) * (u . V)(k) / (|u|^2 + eps)
__global__ void k_combine(){
    int i = blockIdx.x * 256 + threadIdx.x;
    if (i >= M3) return;
    int kz = i & 127, ky = (i >> 7) & 127, kx = i >> 14;
    float ux = (float)(kx < 64 ? kx : kx - 128);
    float uy = (float)(ky < 64 ? ky : ky - 128);
    float uz = (float)(kz < 64 ? kz : kz - 128);
    float us = ux*ux + uy*uy + uz*uz;
    float gk = __expf(-us * (1.0f / 2048.0f));  // 2*(sigma/res)^2 = 1/2048
    float2 vx = g_Vc[i], vy = g_Vc[i + M3], vz = g_Vc[i + 2*M3];
    float dre = ux*vx.x + uy*vy.x + uz*vz.x;
    float dim = ux*vx.y + uy*vy.y + uz*vz.y;
    float s = gk / (2.0f * FPI * (us + 1e-6f));
    g_C[i] = make_float2(s * dim, -s * dre);   // (-i)*(dre + i*dim) scaled
}

__global__ void k_interp(const float* __restrict__ pts, int N){
    int n = blockIdx.x * 256 + threadIdx.x;
    float acc = 0.0f;
    if (n < N){
        float px = pts[3*n], py = pts[3*n+1], pz = pts[3*n+2];
        int ix[2], iy[2], iz[2]; float wx[2], wy[2], wz[2];
        corners(px, py, pz, ix, iy, iz, wx, wy, wz);
        #pragma unroll
        for (int c = 0; c < 8; c++){
            int a = (c >> 2) & 1, b = (c >> 1) & 1, d = c & 1;
            float w = wx[a] * wy[b] * wz[d];
            int idx = (ix[a] << 14) | (iy[b] << 7) | iz[d];
            acc += w * g_chi[idx];
        }
    }
    // block reduce -> one double atomic per block
    #pragma unroll
    for (int o = 16; o > 0; o >>= 1)
        acc += __shfl_down_sync(0xffffffffu, acc, o);
    __shared__ float wsum[8];
    if ((threadIdx.x & 31) == 0) wsum[threadIdx.x >> 5] = acc;
    __syncthreads();
    if (threadIdx.x == 0){
        float s = 0.0f;
        #pragma unroll
        for (int i = 0; i < 8; i++) s += wsum[i];
        atomicAdd(&g_stats[0], (double)s);
    }
}

__global__ void k_finalize(int N){
    double mean = g_stats[0] / (double)N;
    double chi0 = (double)g_chi[0] - mean;
    g_stats[1] = mean;
    g_stats[2] = 0.5 / fabs(chi0);
}

__global__ void k_writeout(float* __restrict__ out){
    int i = blockIdx.x * 256 + threadIdx.x;
    if (i >= M3) return;
    float mean = (float)g_stats[1];
    float sc   = (float)g_stats[2];
    out[i] = sc * (g_chi[i] - mean);
}

// ============================================================================
// launch
// ============================================================================
extern "C" void kernel_launch(void* const* d_in, const int* in_sizes, int n_in,
                              void* d_out, int out_size){
    const float* pts = (const float*)d_in[0];
    const float* nrm = (const float*)d_in[1];
    float* out = (float*)d_out;
    const int N = in_sizes[0] / 3;

    // 1) zero scatter targets + stats
    k_zero<<<6144, 1024>>>();
    // 2) trilinear scatter of normals
    k_scatter<<<(N + 255) / 256, 256>>>(pts, nrm, N);
    // 3) forward 3D FFT of the 3 fields: z, y, x
    k_fft_z_r2c<<<dim3(1024, 1, 3), 128>>>();
    k_fft_strided<-1, 0><<<dim3(8, 128, 3), 128>>>(16384, 128);   // y
    k_fft_strided<-1, 0><<<dim3(8, 128, 3), 128>>>(128, 16384);   // x
    // 4) spectral combine -> chi_tilde
    k_combine<<<(M3 + 255) / 256, 256>>>();
    // 5) inverse 3D FFT: x, y, z (real out, scaled)
    k_fft_strided<1, 1><<<dim3(8, 128, 1), 128>>>(128, 16384);    // x
    k_fft_strided<1, 1><<<dim3(8, 128, 1), 128>>>(16384, 128);    // y
    k_fft_z_c2r<<<1024, 128>>>();
    // 6) gather at points -> mean
    k_interp<<<(N + 255) / 256, 256>>>(pts, N);
    k_finalize<<<1, 1>>>(N);
    // 7) normalize + write
    k_writeout<<<(M3 + 255) / 256, 256>>>(out);
}

// round 2
// speedup vs baseline: 1.1362x; 1.1362x over previous
#include <cuda_runtime.h>

// ============================================================================
// DPSR: trilinear scatter -> 3D FFT -> spectral Poisson -> iFFT -> gather/norm
// res = 128, sigma = 2, eps = 1e-6, B = 1, N = 250000, F = 3
//
// Round 2: twiddle tables (no in-loop sincos) + pack vx+i*vy into ONE complex
// FFT (Hermitian unpack in combine). Forward passes: 9 -> 6.
// ============================================================================

#define RESN 128
#define M3   2097152          // 128^3
#define FPI  3.14159265358979f

// ---- scratch (device globals; no allocation allowed) ----
__device__ float2 g_wv[M3];         // packed field vx + i*vy; becomes W(k) in-place (16 MB)
__device__ float  g_vzr[M3];        // scattered vz (8 MB)
__device__ float2 g_Vz[M3];         // spectrum of vz (16 MB)
__device__ float2 g_C[M3];          // chi_tilde (16 MB)
__device__ float  g_chi[M3];        // chi_prime (8 MB)
__device__ double g_stats[4];       // [0]=sum(chi_c), [1]=mean, [2]=scale

// ---- complex helpers ----
__device__ __forceinline__ float2 cadd(float2 a, float2 b){ return make_float2(a.x+b.x, a.y+b.y); }
__device__ __forceinline__ float2 csub(float2 a, float2 b){ return make_float2(a.x-b.x, a.y-b.y); }
__device__ __forceinline__ float2 cmul(float2 a, float2 b){
    return make_float2(a.x*b.x - a.y*b.y, a.x*b.y + a.y*b.x);
}

// twiddle lookup: tw[j] = exp(-i*2*pi*j/128), j in [0,64).
// forward (DIR=-1) uses it directly; inverse conjugates.
template<int DIR>
__device__ __forceinline__ float2 TWL(const float2* __restrict__ tw, int idx){
    float2 w = tw[idx];
    return (DIR < 0) ? w : make_float2(w.x, -w.y);
}

// fill shared twiddle table; caller must __syncthreads() afterwards.
__device__ __forceinline__ void fill_tw(float2* s_tw){
    if (threadIdx.x < 64){
        float s, c;
        __sincosf(-(FPI / 64.0f) * (float)threadIdx.x, &s, &c);
        s_tw[threadIdx.x] = make_float2(c, s);
    }
}

// ============================================================================
// 128-point radix-2 DIF FFT over tile[pos][line], 16 lines per block,
// 128 threads: t = tid>>4 in [0,8), line = tid&15.
// First 4 stages (strides 64/32/16/8) intra-thread on v[m]=tile[t+8m];
// one shared exchange to contiguous 8-blocks; 3 more stages; bit-reversed store.
// ============================================================================
template<int DIR>
__device__ __forceinline__ void fft128_tile(float2 (*tile)[17],
                                            const float2* __restrict__ tw){
    const int tid = threadIdx.x;
    const int t   = tid >> 4;      // 0..7  : sub-lane within line
    const int ln  = tid & 15;      // 0..15 : line

    float2 v[16];
    #pragma unroll
    for (int m = 0; m < 16; m++) v[m] = tile[t + 8*m][ln];

    // stage h=64 : pairs (m, m+8), twiddle index j = t+8m
    #pragma unroll
    for (int m = 0; m < 8; m++){
        float2 a = v[m], b = v[m+8];
        v[m]   = cadd(a, b);
        v[m+8] = cmul(csub(a, b), TWL<DIR>(tw, t + 8*m));
    }
    // stage h=32 : idx = 2*(t + 8*m2)
    #pragma unroll
    for (int h = 0; h < 16; h += 8)
    #pragma unroll
    for (int m2 = 0; m2 < 4; m2++){
        int m = h + m2;
        float2 a = v[m], b = v[m+4];
        v[m]   = cadd(a, b);
        v[m+4] = cmul(csub(a, b), TWL<DIR>(tw, 2*(t + 8*m2)));
    }
    // stage h=16 : idx = 4*(t + 8*m2)
    #pragma unroll
    for (int h = 0; h < 16; h += 4)
    #pragma unroll
    for (int m2 = 0; m2 < 2; m2++){
        int m = h + m2;
        float2 a = v[m], b = v[m+2];
        v[m]   = cadd(a, b);
        v[m+2] = cmul(csub(a, b), TWL<DIR>(tw, 4*(t + 8*m2)));
    }
    // stage h=8 : idx = 8*t (same twiddle for all pairs in thread)
    {
        float2 w8 = TWL<DIR>(tw, 8*t);
        #pragma unroll
        for (int h = 0; h < 16; h += 2){
            float2 a = v[h], b = v[h+1];
            v[h]   = cadd(a, b);
            v[h+1] = cmul(csub(a, b), w8);
        }
    }

    // exchange: re-own as two contiguous 8-blocks starting at 16t.
    #pragma unroll
    for (int m = 0; m < 16; m++) tile[t + 8*m][ln] = v[m];
    __syncthreads();
    #pragma unroll
    for (int r = 0; r < 16; r++) v[r] = tile[16*t + r][ln];

    // stage h=4 : per 8-block, pairs (r, r+4), idx = 16*r
    #pragma unroll
    for (int r0 = 0; r0 < 16; r0 += 8)
    #pragma unroll
    for (int r = 0; r < 4; r++){
        float2 a = v[r0+r], b = v[r0+r+4];
        v[r0+r]   = cadd(a, b);
        v[r0+r+4] = cmul(csub(a, b), TWL<DIR>(tw, 16*r));
    }
    // stage h=2 : twiddles 1 and (0, -+1)
    {
        const float2 wi = make_float2(0.0f, (DIR < 0) ? -1.0f : 1.0f);
        #pragma unroll
        for (int r0 = 0; r0 < 16; r0 += 4){
            float2 a = v[r0],   b = v[r0+2];
            v[r0]   = cadd(a, b);
            v[r0+2] = csub(a, b);
            a = v[r0+1]; b = v[r0+3];
            v[r0+1] = cadd(a, b);
            v[r0+3] = cmul(csub(a, b), wi);
        }
    }
    // stage h=1 : trivial
    #pragma unroll
    for (int r0 = 0; r0 < 16; r0 += 2){
        float2 a = v[r0], b = v[r0+1];
        v[r0]   = cadd(a, b);
        v[r0+1] = csub(a, b);
    }

    __syncthreads();   // all exchange-reads done before bitrev writes
    // output position p = 16t + r belongs to k = rev4(r)*8 + rev3(t)
    const int rev3t = ((t & 1) << 2) | (t & 2) | ((t & 4) >> 2);
    #pragma unroll
    for (int r = 0; r < 16; r++){
        int rr = ((r & 1) << 3) | ((r & 2) << 1) | ((r & 4) >> 1) | ((r & 8) >> 3);
        tile[8*rr + rev3t][ln] = v[r];
    }
    __syncthreads();
}

// ============================================================================
// FFT kernels
// ============================================================================

// z-axis forward on packed complex field g_wv, in place.
__global__ void __launch_bounds__(128) k_fft_z_packed(){
    __shared__ float2 tile[128][17];
    __shared__ float2 s_tw[64];
    fill_tw(s_tw);
    const int base = blockIdx.x * 2048;
    for (int i = threadIdx.x; i < 2048; i += 128)
        tile[i & 127][i >> 7] = g_wv[base + i];
    __syncthreads();
    fft128_tile<-1>(tile, s_tw);
    for (int i = threadIdx.x; i < 2048; i += 128)
        g_wv[base + i] = tile[i & 127][i >> 7];
}

// z-axis forward, real vz -> complex g_Vz.
__global__ void __launch_bounds__(128) k_fft_z_r2c(){
    __shared__ float2 tile[128][17];
    __shared__ float2 s_tw[64];
    fill_tw(s_tw);
    const int base = blockIdx.x * 2048;
    for (int i = threadIdx.x; i < 2048; i += 128)
        tile[i & 127][i >> 7] = make_float2(g_vzr[base + i], 0.0f);
    __syncthreads();
    fft128_tile<-1>(tile, s_tw);
    for (int i = threadIdx.x; i < 2048; i += 128)
        g_Vz[base + i] = tile[i & 127][i >> 7];
}

// z-axis inverse, complex g_C -> real g_chi (with 1/128^3 scaling).
__global__ void __launch_bounds__(128) k_fft_z_c2r(){
    __shared__ float2 tile[128][17];
    __shared__ float2 s_tw[64];
    fill_tw(s_tw);
    const int base = blockIdx.x * 2048;
    for (int i = threadIdx.x; i < 2048; i += 128)
        tile[i & 127][i >> 7] = g_C[base + i];
    __syncthreads();
    fft128_tile<1>(tile, s_tw);
    const float sc = 1.0f / 2097152.0f;
    for (int i = threadIdx.x; i < 2048; i += 128)
        g_chi[base + i] = tile[i & 127][i >> 7].x * sc;
}

// strided axis (y: bstride=16384, estride=128; x: bstride=128, estride=16384)
// WHICH==0: forward fields, blockIdx.z selects g_wv / g_Vz.
// WHICH==1: g_C. In-place.
template<int DIR, int WHICH>
__global__ void __launch_bounds__(128) k_fft_strided(int bstride, int estride){
    __shared__ float2 tile[128][17];
    __shared__ float2 s_tw[64];
    fill_tw(s_tw);
    float2* g = (WHICH == 0) ? (blockIdx.z ? g_Vz : g_wv) : g_C;
    const int base = blockIdx.y * bstride + blockIdx.x * 16;
    for (int i = threadIdx.x; i < 2048; i += 128){
        int e = i >> 4, d = i & 15;
        tile[e][d] = g[base + e * estride + d];
    }
    __syncthreads();
    fft128_tile<DIR>(tile, s_tw);
    for (int i = threadIdx.x; i < 2048; i += 128){
        int e = i >> 4, d = i & 15;
        g[base + e * estride + d] = tile[e][d];
    }
}

// ============================================================================
// Pipeline kernels
// ============================================================================

__global__ void k_init(){
    int i = blockIdx.x * 1024 + threadIdx.x;
    float4 z4 = make_float4(0.f, 0.f, 0.f, 0.f);
    // g_wv: 4M floats = 1M float4 ; g_vzr: 2M floats = 512K float4
    if (i < 1048576)  reinterpret_cast<float4*>(g_wv)[i] = z4;
    if (i < 524288)   reinterpret_cast<float4*>(g_vzr)[i] = z4;
    if (i < 4)        g_stats[i] = 0.0;
}

// trilinear corner setup shared by scatter/gather
__device__ __forceinline__ void corners(float px, float py, float pz,
                                        int ix[2], int iy[2], int iz[2],
                                        float wx[2], float wy[2], float wz[2]){
    float prx = px * 128.0f, pry = py * 128.0f, prz = pz * 128.0f;
    float lox = floorf(prx), loy = floorf(pry), loz = floorf(prz);
    ix[0] = ((int)lox) & 127;  iy[0] = ((int)loy) & 127;  iz[0] = ((int)loz) & 127;
    ix[1] = ((int)ceilf(prx)) & 127;
    iy[1] = ((int)ceilf(pry)) & 127;
    iz[1] = ((int)ceilf(prz)) & 127;
    float fx = prx - lox, fy = pry - loy, fz = prz - loz;
    wx[0] = 1.0f - fx; wx[1] = fx;
    wy[0] = 1.0f - fy; wy[1] = fy;
    wz[0] = 1.0f - fz; wz[1] = fz;
}

__global__ void k_scatter(const float* __restrict__ pts,
                          const float* __restrict__ nrm, int N){
    int n = blockIdx.x * 256 + threadIdx.x;
    if (n >= N) return;
    float px = pts[3*n], py = pts[3*n+1], pz = pts[3*n+2];
    float nx = nrm[3*n], ny = nrm[3*n+1], nz = nrm[3*n+2];
    int ix[2], iy[2], iz[2]; float wx[2], wy[2], wz[2];
    corners(px, py, pz, ix, iy, iz, wx, wy, wz);
    #pragma unroll
    for (int c = 0; c < 8; c++){
        int a = (c >> 2) & 1, b = (c >> 1) & 1, d = c & 1;
        float w = wx[a] * wy[b] * wz[d];
        int idx = (ix[a] << 14) | (iy[b] << 7) | iz[d];
        atomicAdd(&g_wv[idx].x, w * nx);
        atomicAdd(&g_wv[idx].y, w * ny);
        atomicAdd(&g_vzr[idx],  w * nz);
    }
}

// chi_tilde = g(k) * (-i/(2pi)) * (u . V)(k) / (|u|^2 + eps)
// with Vx,Vy recovered from packed spectrum W: Vx=(A+conj(B'))/2, Vy=-i(A-conj(B'))/2
// where A=W(k), B'=W(-k). Mirror read hits L2 (16 MB spectrum is L2-resident).
__global__ void k_combine(){
    int i = blockIdx.x * 256 + threadIdx.x;
    if (i >= M3) return;
    int kz = i & 127, ky = (i >> 7) & 127, kx = i >> 14;
    int im = (((128 - kx) & 127) << 14) | (((128 - ky) & 127) << 7) | ((128 - kz) & 127);

    float2 A  = g_wv[i];
    float2 Bm = g_wv[im];
    float2 B  = make_float2(Bm.x, -Bm.y);      // conj(W(-k))
    float2 S  = cadd(A, B);
    float2 D  = csub(A, B);
    float2 Vx = make_float2(0.5f * S.x, 0.5f * S.y);
    float2 Vy = make_float2(0.5f * D.y, -0.5f * D.x);   // -i*D/2
    float2 Vz = g_Vz[i];

    float ux = (float)(kx < 64 ? kx : kx - 128);
    float uy = (float)(ky < 64 ? ky : ky - 128);
    float uz = (float)(kz < 64 ? kz : kz - 128);
    float us = ux*ux + uy*uy + uz*uz;
    float gk = __expf(-us * (1.0f / 2048.0f));  // 2*(sigma/res)^2 = 1/2048

    float dre = ux*Vx.x + uy*Vy.x + uz*Vz.x;
    float dim = ux*Vx.y + uy*Vy.y + uz*Vz.y;
    float s = gk / (2.0f * FPI * (us + 1e-6f));
    g_C[i] = make_float2(s * dim, -s * dre);   // (-i)*(dre + i*dim) scaled
}

__global__ void k_interp(const float* __restrict__ pts, int N){
    int n = blockIdx.x * 256 + threadIdx.x;
    float acc = 0.0f;
    if (n < N){
        float px = pts[3*n], py = pts[3*n+1], pz = pts[3*n+2];
        int ix[2], iy[2], iz[2]; float wx[2], wy[2], wz[2];
        corners(px, py, pz, ix, iy, iz, wx, wy, wz);
        #pragma unroll
        for (int c = 0; c < 8; c++){
            int a = (c >> 2) & 1, b = (c >> 1) & 1, d = c & 1;
            float w = wx[a] * wy[b] * wz[d];
            int idx = (ix[a] << 14) | (iy[b] << 7) | iz[d];
            acc += w * g_chi[idx];
        }
    }
    // block reduce -> one double atomic per block
    #pragma unroll
    for (int o = 16; o > 0; o >>= 1)
        acc += __shfl_down_sync(0xffffffffu, acc, o);
    __shared__ float wsum[8];
    if ((threadIdx.x & 31) == 0) wsum[threadIdx.x >> 5] = acc;
    __syncthreads();
    if (threadIdx.x == 0){
        float s = 0.0f;
        #pragma unroll
        for (int i = 0; i < 8; i++) s += wsum[i];
        atomicAdd(&g_stats[0], (double)s);
    }
}

__global__ void k_finalize(int N){
    double mean = g_stats[0] / (double)N;
    double chi0 = (double)g_chi[0] - mean;
    g_stats[1] = mean;
    g_stats[2] = 0.5 / fabs(chi0);
}

__global__ void k_writeout(float* __restrict__ out){
    int i = blockIdx.x * 256 + threadIdx.x;
    if (i >= M3) return;
    float mean = (float)g_stats[1];
    float sc   = (float)g_stats[2];
    out[i] = sc * (g_chi[i] - mean);
}

// ============================================================================
// launch
// ============================================================================
extern "C" void kernel_launch(void* const* d_in, const int* in_sizes, int n_in,
                              void* d_out, int out_size){
    const float* pts = (const float*)d_in[0];
    const float* nrm = (const float*)d_in[1];
    float* out = (float*)d_out;
    const int N = in_sizes[0] / 3;

    // 1) zero scatter targets + stats
    k_init<<<1024, 1024>>>();
    // 2) trilinear scatter: (nx,ny) into packed complex g_wv, nz into g_vzr
    k_scatter<<<(N + 255) / 256, 256>>>(pts, nrm, N);
    // 3) forward 3D FFT: z on both fields, then y, x (2 fields per launch)
    k_fft_z_packed<<<1024, 128>>>();
    k_fft_z_r2c<<<1024, 128>>>();
    k_fft_strided<-1, 0><<<dim3(8, 128, 2), 128>>>(16384, 128);   // y
    k_fft_strided<-1, 0><<<dim3(8, 128, 2), 128>>>(128, 16384);   // x
    // 4) spectral combine (Hermitian unpack of vx,vy) -> chi_tilde
    k_combine<<<(M3 + 255) / 256, 256>>>();
    // 5) inverse 3D FFT: x, y, z (real out, scaled)
    k_fft_strided<1, 1><<<dim3(8, 128, 1), 128>>>(128, 16384);    // x
    k_fft_strided<1, 1><<<dim3(8, 128, 1), 128>>>(16384, 128);    // y
    k_fft_z_c2r<<<1024, 128>>>();
    // 6) gather at points -> mean
    k_interp<<<(N + 255) / 256, 256>>>(pts, N);
    k_finalize<<<1, 1>>>(N);
    // 7) normalize + write
    k_writeout<<<(M3 + 255) / 256, 256>>>(out);
}

// round 3
// speedup vs baseline: 1.1444x; 1.0072x over previous
#include <cuda_runtime.h>

// ============================================================================
// DPSR: trilinear scatter -> 3D FFT -> spectral Poisson -> iFFT -> gather/norm
// res = 128, sigma = 2, eps = 1e-6, B = 1, N = 250000, F = 3
//
// Round 3: 16-thread/line FFT (256-thread blocks, shfl stage-8, swizzled
// shared tile), fused combine+x-inverse, merged z-forward launches.
// ============================================================================

#define M3   2097152          // 128^3
#define FPI  3.14159265358979f

// ---- scratch (device globals; no allocation allowed) ----
__device__ float2 g_wv[M3];         // packed field vx + i*vy -> W(k) in place
__device__ float  g_vzr[M3];        // scattered vz
__device__ float2 g_Vz[M3];         // spectrum of vz
__device__ float2 g_C[M3];          // chi_tilde (after fused combine + x-inv)
__device__ float  g_chi[M3];        // chi_prime
__device__ double g_stats[4];       // [0]=sum(chi_c), [1]=mean, [2]=scale

// ---- complex helpers ----
__device__ __forceinline__ float2 cadd(float2 a, float2 b){ return make_float2(a.x+b.x, a.y+b.y); }
__device__ __forceinline__ float2 csub(float2 a, float2 b){ return make_float2(a.x-b.x, a.y-b.y); }
__device__ __forceinline__ float2 cmul(float2 a, float2 b){
    return make_float2(a.x*b.x - a.y*b.y, a.x*b.y + a.y*b.x);
}

// tw[j] = exp(-i*2*pi*j/128), j in [0,64). Inverse conjugates.
template<int DIR>
__device__ __forceinline__ float2 TWL(const float2* __restrict__ tw, int idx){
    float2 w = tw[idx];
    return (DIR < 0) ? w : make_float2(w.x, -w.y);
}

__device__ __forceinline__ void fill_tw(float2* s_tw){
    if (threadIdx.x < 64){
        float s, c;
        __sincosf(-(FPI / 64.0f) * (float)threadIdx.x, &s, &c);
        s_tw[threadIdx.x] = make_float2(c, s);
    }
}

// shared-tile column swizzle: XOR bits [3:1] with bits [6:4] -> conflict-free
#define SWZ(c) ((c) ^ ((((unsigned)(c)) & 0x70u) >> 3))

// ============================================================================
// 128-pt radix-2 DIF FFT, 16 lines per 256-thread block.
// t = tid&15 (sub-lane), ln = tid>>4 (line). Thread owns x[t+16m], m=0..7.
// Stages 64/32/16 intra-thread; stage 8 via shfl_xor(8) (lane pair in-warp);
// shared exchange to contiguous-8 ownership; stages 4/2/1; bit-rev store.
// Caller fills tile[ln][SWZ(pos)], syncs, calls; results left in
// tile[ln][SWZ(k)]; function ends with a final __syncthreads().
// ============================================================================
template<int DIR>
__device__ __forceinline__ void fft128_tile16(float2 (*tile)[129],
                                              const float2* __restrict__ s_tw){
    const int tid = threadIdx.x;
    const int t   = tid & 15;
    const int ln  = tid >> 4;

    float2 v[8];
    #pragma unroll
    for (int m = 0; m < 8; m++) v[m] = tile[ln][SWZ(t + 16*m)];

    // stage h=64 : pairs (m, m+4), tw idx = p = t+16m (m<4)
    #pragma unroll
    for (int m = 0; m < 4; m++){
        float2 a = v[m], b = v[m+4];
        v[m]   = cadd(a, b);
        v[m+4] = cmul(csub(a, b), TWL<DIR>(s_tw, t + 16*m));
    }
    // stage h=32 : pairs (m, m+2) within halves, idx = 2*(t+16*(m&1))
    #pragma unroll
    for (int g = 0; g < 8; g += 4)
    #pragma unroll
    for (int m2 = 0; m2 < 2; m2++){
        int m = g + m2;
        float2 a = v[m], b = v[m+2];
        v[m]   = cadd(a, b);
        v[m+2] = cmul(csub(a, b), TWL<DIR>(s_tw, 2*(t + 16*m2)));
    }
    // stage h=16 : pairs (m, m+1), idx = 4*t
    {
        float2 w = TWL<DIR>(s_tw, 4*t);
        #pragma unroll
        for (int m = 0; m < 8; m += 2){
            float2 a = v[m], b = v[m+1];
            v[m]   = cadd(a, b);
            v[m+1] = cmul(csub(a, b), w);
        }
    }
    // stage h=8 : cross-thread (t <-> t^8) via shfl_xor; idx = 8*(t&7)
    {
        float2 w = TWL<DIR>(s_tw, 8*(t & 7));
        const bool hi = (t & 8) != 0;
        #pragma unroll
        for (int m = 0; m < 8; m++){
            float ox = __shfl_xor_sync(0xffffffffu, v[m].x, 8);
            float oy = __shfl_xor_sync(0xffffffffu, v[m].y, 8);
            if (!hi) v[m] = make_float2(v[m].x + ox, v[m].y + oy);
            else     v[m] = cmul(make_float2(ox - v[m].x, oy - v[m].y), w);
        }
    }

    // exchange: re-own positions 8t..8t+7
    #pragma unroll
    for (int m = 0; m < 8; m++) tile[ln][SWZ(t + 16*m)] = v[m];
    __syncthreads();
    #pragma unroll
    for (int r = 0; r < 8; r++) v[r] = tile[ln][SWZ(8*t + r)];

    // stage h=4 : pairs (r, r+4), idx = 16*r
    #pragma unroll
    for (int r = 0; r < 4; r++){
        float2 a = v[r], b = v[r+4];
        v[r]   = cadd(a, b);
        v[r+4] = cmul(csub(a, b), TWL<DIR>(s_tw, 16*r));
    }
    // stage h=2 : even r -> w=1, odd r -> w = (0, -+1)
    {
        const float2 wi = make_float2(0.0f, (DIR < 0) ? -1.0f : 1.0f);
        #pragma unroll
        for (int r0 = 0; r0 < 8; r0 += 4){
            float2 a = v[r0],   b = v[r0+2];
            v[r0]   = cadd(a, b);
            v[r0+2] = csub(a, b);
            a = v[r0+1]; b = v[r0+3];
            v[r0+1] = cadd(a, b);
            v[r0+3] = cmul(csub(a, b), wi);
        }
    }
    // stage h=1
    #pragma unroll
    for (int r0 = 0; r0 < 8; r0 += 2){
        float2 a = v[r0], b = v[r0+1];
        v[r0]   = cadd(a, b);
        v[r0+1] = csub(a, b);
    }

    __syncthreads();   // exchange reads done before bitrev writes
    // position p = 8t + r -> k = rev3(r)*16 + rev4(t)
    const int r4t = ((t & 1) << 3) | ((t & 2) << 1) | ((t & 4) >> 1) | ((t & 8) >> 3);
    #pragma unroll
    for (int r = 0; r < 8; r++){
        int r3 = ((r & 1) << 2) | (r & 2) | ((r & 4) >> 2);
        tile[ln][SWZ(16*r3 + r4t)] = v[r];
    }
    __syncthreads();
}

// ============================================================================
// FFT kernels (all 256 threads, 16 lines/block)
// ============================================================================

// z-axis forward: blockIdx.y==0 -> g_wv in place (complex),
//                 blockIdx.y==1 -> g_vzr (real) -> g_Vz.
__global__ void __launch_bounds__(256) k_fft_z_fwd(){
    __shared__ float2 tile[16][129];
    __shared__ float2 s_tw[64];
    fill_tw(s_tw);
    const int base = blockIdx.x * 2048;
    if (blockIdx.y == 0){
        for (int i = threadIdx.x; i < 2048; i += 256)
            tile[i >> 7][SWZ(i & 127)] = g_wv[base + i];
    } else {
        for (int i = threadIdx.x; i < 2048; i += 256)
            tile[i >> 7][SWZ(i & 127)] = make_float2(g_vzr[base + i], 0.0f);
    }
    __syncthreads();
    fft128_tile16<-1>(tile, s_tw);
    if (blockIdx.y == 0){
        for (int i = threadIdx.x; i < 2048; i += 256)
            g_wv[base + i] = tile[i >> 7][SWZ(i & 127)];
    } else {
        for (int i = threadIdx.x; i < 2048; i += 256)
            g_Vz[base + i] = tile[i >> 7][SWZ(i & 127)];
    }
}

// z-axis inverse, g_C -> real g_chi (scaled by 1/128^3).
__global__ void __launch_bounds__(256) k_fft_z_c2r(){
    __shared__ float2 tile[16][129];
    __shared__ float2 s_tw[64];
    fill_tw(s_tw);
    const int base = blockIdx.x * 2048;
    for (int i = threadIdx.x; i < 2048; i += 256)
        tile[i >> 7][SWZ(i & 127)] = g_C[base + i];
    __syncthreads();
    fft128_tile16<1>(tile, s_tw);
    const float sc = 1.0f / 2097152.0f;
    for (int i = threadIdx.x; i < 2048; i += 256)
        g_chi[base + i] = tile[i >> 7][SWZ(i & 127)].x * sc;
}

// strided axis, in place. WHICH==0: forward fields (blockIdx.z: g_wv/g_Vz);
// WHICH==1: g_C.
template<int DIR, int WHICH>
__global__ void __launch_bounds__(256) k_fft_strided(int bstride, int estride){
    __shared__ float2 tile[16][129];
    __shared__ float2 s_tw[64];
    fill_tw(s_tw);
    float2* g = (WHICH == 0) ? (blockIdx.z ? g_Vz : g_wv) : g_C;
    const int base = blockIdx.y * bstride + blockIdx.x * 16;
    for (int i = threadIdx.x; i < 2048; i += 256){
        int e = i >> 4, d = i & 15;
        tile[d][SWZ(e)] = g[base + e * estride + d];
    }
    __syncthreads();
    fft128_tile16<DIR>(tile, s_tw);
    for (int i = threadIdx.x; i < 2048; i += 256){
        int e = i >> 4, d = i & 15;
        g[base + e * estride + d] = tile[d][SWZ(e)];
    }
}

// Fused spectral combine + inverse x-pass. Block: ky = blockIdx.y,
// kz tile = blockIdx.x*16. Reads g_wv (+ Hermitian mirror) and g_Vz,
// computes chi_tilde into the tile, inverse-FFTs along kx, writes g_C.
__global__ void __launch_bounds__(256) k_xinv_combine(){
    __shared__ float2 tile[16][129];
    __shared__ float2 s_tw[64];
    fill_tw(s_tw);
    const int ky  = blockIdx.y;
    const int kzb = blockIdx.x * 16;
    const int kym = (128 - ky) & 127;
    const int base = ky * 128 + kzb;
    for (int i = threadIdx.x; i < 2048; i += 256){
        int kx = i >> 4, d = i & 15;
        int kz  = kzb + d;
        int idx = kx * 16384 + base + d;
        int im  = ((128 - kx) & 127) * 16384 + kym * 128 + ((128 - kz) & 127);

        float2 A  = g_wv[idx];
        float2 Bm = g_wv[im];
        float2 Vz = g_Vz[idx];
        // Vx = (A + conj(Bm))/2 ; Vy = -i*(A - conj(Bm))/2
        float2 S = make_float2(A.x + Bm.x, A.y - Bm.y);
        float2 D = make_float2(A.x - Bm.x, A.y + Bm.y);
        float2 Vx = make_float2(0.5f * S.x, 0.5f * S.y);
        float2 Vy = make_float2(0.5f * D.y, -0.5f * D.x);

        float ux = (float)(kx < 64 ? kx : kx - 128);
        float uy = (float)(ky < 64 ? ky : ky - 128);
        float uz = (float)(kz < 64 ? kz : kz - 128);
        float us = ux*ux + uy*uy + uz*uz;
        float gk = __expf(-us * (1.0f / 2048.0f));

        float dre = ux*Vx.x + uy*Vy.x + uz*Vz.x;
        float dim = ux*Vx.y + uy*Vy.y + uz*Vz.y;
        float s = gk / (2.0f * FPI * (us + 1e-6f));
        tile[d][SWZ(kx)] = make_float2(s * dim, -s * dre);
    }
    __syncthreads();
    fft128_tile16<1>(tile, s_tw);
    for (int i = threadIdx.x; i < 2048; i += 256){
        int e = i >> 4, d = i & 15;
        g_C[base + e * 16384 + d] = tile[d][SWZ(e)];
    }
}

// ============================================================================
// Pipeline kernels
// ============================================================================

__global__ void k_init(){
    int i = blockIdx.x * 1024 + threadIdx.x;
    float4 z4 = make_float4(0.f, 0.f, 0.f, 0.f);
    if (i < 1048576) reinterpret_cast<float4*>(g_wv)[i] = z4;
    else             reinterpret_cast<float4*>(g_vzr)[i - 1048576] = z4;
    if (i < 4)       g_stats[i] = 0.0;
}

__device__ __forceinline__ void corners(float px, float py, float pz,
                                        int ix[2], int iy[2], int iz[2],
                                        float wx[2], float wy[2], float wz[2]){
    float prx = px * 128.0f, pry = py * 128.0f, prz = pz * 128.0f;
    float lox = floorf(prx), loy = floorf(pry), loz = floorf(prz);
    ix[0] = ((int)lox) & 127;  iy[0] = ((int)loy) & 127;  iz[0] = ((int)loz) & 127;
    ix[1] = ((int)ceilf(prx)) & 127;
    iy[1] = ((int)ceilf(pry)) & 127;
    iz[1] = ((int)ceilf(prz)) & 127;
    float fx = prx - lox, fy = pry - loy, fz = prz - loz;
    wx[0] = 1.0f - fx; wx[1] = fx;
    wy[0] = 1.0f - fy; wy[1] = fy;
    wz[0] = 1.0f - fz; wz[1] = fz;
}

__global__ void k_scatter(const float* __restrict__ pts,
                          const float* __restrict__ nrm, int N){
    int n = blockIdx.x * 256 + threadIdx.x;
    if (n >= N) return;
    float px = pts[3*n], py = pts[3*n+1], pz = pts[3*n+2];
    float nx = nrm[3*n], ny = nrm[3*n+1], nz = nrm[3*n+2];
    int ix[2], iy[2], iz[2]; float wx[2], wy[2], wz[2];
    corners(px, py, pz, ix, iy, iz, wx, wy, wz);
    #pragma unroll
    for (int c = 0; c < 8; c++){
        int a = (c >> 2) & 1, b = (c >> 1) & 1, d = c & 1;
        float w = wx[a] * wy[b] * wz[d];
        int idx = (ix[a] << 14) | (iy[b] << 7) | iz[d];
        atomicAdd(&g_wv[idx].x, w * nx);
        atomicAdd(&g_wv[idx].y, w * ny);
        atomicAdd(&g_vzr[idx],  w * nz);
    }
}

__global__ void k_interp(const float* __restrict__ pts, int N){
    int n = blockIdx.x * 256 + threadIdx.x;
    float acc = 0.0f;
    if (n < N){
        float px = pts[3*n], py = pts[3*n+1], pz = pts[3*n+2];
        int ix[2], iy[2], iz[2]; float wx[2], wy[2], wz[2];
        corners(px, py, pz, ix, iy, iz, wx, wy, wz);
        #pragma unroll
        for (int c = 0; c < 8; c++){
            int a = (c >> 2) & 1, b = (c >> 1) & 1, d = c & 1;
            float w = wx[a] * wy[b] * wz[d];
            int idx = (ix[a] << 14) | (iy[b] << 7) | iz[d];
            acc += w * g_chi[idx];
        }
    }
    #pragma unroll
    for (int o = 16; o > 0; o >>= 1)
        acc += __shfl_down_sync(0xffffffffu, acc, o);
    __shared__ float wsum[8];
    if ((threadIdx.x & 31) == 0) wsum[threadIdx.x >> 5] = acc;
    __syncthreads();
    if (threadIdx.x == 0){
        float s = 0.0f;
        #pragma unroll
        for (int i = 0; i < 8; i++) s += wsum[i];
        atomicAdd(&g_stats[0], (double)s);
    }
}

__global__ void k_finalize(int N){
    double mean = g_stats[0] / (double)N;
    double chi0 = (double)g_chi[0] - mean;
    g_stats[1] = mean;
    g_stats[2] = 0.5 / fabs(chi0);
}

__global__ void k_writeout(float* __restrict__ out){
    int i = blockIdx.x * 256 + threadIdx.x;
    if (i >= M3) return;
    float mean = (float)g_stats[1];
    float sc   = (float)g_stats[2];
    out[i] = sc * (g_chi[i] - mean);
}

// ============================================================================
// launch
// ============================================================================
extern "C" void kernel_launch(void* const* d_in, const int* in_sizes, int n_in,
                              void* d_out, int out_size){
    const float* pts = (const float*)d_in[0];
    const float* nrm = (const float*)d_in[1];
    float* out = (float*)d_out;
    const int N = in_sizes[0] / 3;

    k_init<<<1536, 1024>>>();
    k_scatter<<<(N + 255) / 256, 256>>>(pts, nrm, N);
    // forward: z (both fields), y, x
    k_fft_z_fwd<<<dim3(1024, 2), 256>>>();
    k_fft_strided<-1, 0><<<dim3(8, 128, 2), 256>>>(16384, 128);   // y
    k_fft_strided<-1, 0><<<dim3(8, 128, 2), 256>>>(128, 16384);   // x
    // fused combine + inverse x
    k_xinv_combine<<<dim3(8, 128), 256>>>();
    // inverse: y, z
    k_fft_strided<1, 1><<<dim3(8, 128, 1), 256>>>(16384, 128);    // y
    k_fft_z_c2r<<<1024, 256>>>();
    // gather, normalize, write
    k_interp<<<(N + 255) / 256, 256>>>(pts, N);
    k_finalize<<<1, 1>>>(N);
    k_writeout<<<(M3 + 255) / 256, 256>>>(out);
}

// round 4
// speedup vs baseline: 1.1793x; 1.0305x over previous
#include <cuda_runtime.h>

// ============================================================================
// DPSR: trilinear scatter -> 3D FFT -> spectral Poisson -> iFFT -> gather/norm
// res = 128, sigma = 2, eps = 1e-6, B = 1, N = 250000, F = 3
//
// Round 4: all-register FFT (shfl for strides 8/4/2/1, no shared exchange),
// z-axis passes fully direct-global (zero smem staging), strided passes
// with 4 shared ops/elem instead of 6.
// ============================================================================

#define M3   2097152          // 128^3
#define FPI  3.14159265358979f

// ---- scratch: float4-typed for aligned vector access ----
__device__ float4 g_b_wv[M3/2];    // packed vx + i*vy -> W(k)
__device__ float4 g_b_Vz[M3/2];    // spectrum of vz
__device__ float4 g_b_C[M3/2];     // chi_tilde
__device__ float4 g_b_vzr[M3/4];   // scattered vz (real)
__device__ float4 g_b_chi[M3/4];   // chi_prime (real)
__device__ double g_stats[4];

#define g_wv  ((float2*)g_b_wv)
#define g_Vz  ((float2*)g_b_Vz)
#define g_C   ((float2*)g_b_C)
#define g_vzr ((float*)g_b_vzr)
#define g_chi ((float*)g_b_chi)

// ---- complex helpers ----
__device__ __forceinline__ float2 cadd(float2 a, float2 b){ return make_float2(a.x+b.x, a.y+b.y); }
__device__ __forceinline__ float2 csub(float2 a, float2 b){ return make_float2(a.x-b.x, a.y-b.y); }
__device__ __forceinline__ float2 cmul(float2 a, float2 b){
    return make_float2(a.x*b.x - a.y*b.y, a.x*b.y + a.y*b.x);
}

template<int DIR>
__device__ __forceinline__ float2 TWL(const float2* __restrict__ tw, int idx){
    float2 w = tw[idx];
    return (DIR < 0) ? w : make_float2(w.x, -w.y);
}

__device__ __forceinline__ void fill_tw(float2* s_tw){
    if (threadIdx.x < 64){
        float s, c;
        __sincosf(-(FPI / 64.0f) * (float)threadIdx.x, &s, &c);
        s_tw[threadIdx.x] = make_float2(c, s);
    }
}

__device__ __forceinline__ int rev4(int t){
    return ((t & 1) << 3) | ((t & 2) << 1) | ((t & 4) >> 1) | ((t & 8) >> 3);
}

#define SWZ(c) ((c) ^ ((((unsigned)(c)) & 0x70u) >> 3))

// ============================================================================
// 128-pt radix-2 DIF FFT entirely in registers + shuffles.
// 16 lanes per line (t = lane-in-group), thread owns x[t + 16m], m=0..7.
// Stages 64/32/16 intra-thread; stages 8/4/2/1 via shfl_xor (in-warp).
// On return: v[m] = X[8*rev4(t) + rev3(m)]  (rev3 order: 0,4,2,6,1,5,3,7).
// ============================================================================
template<int DIR>
__device__ __forceinline__ void fft128_shfl(float2 v[8], int t,
                                            const float2* __restrict__ s_tw){
    // stage h=64 : pairs (m, m+4), idx = t+16m
    #pragma unroll
    for (int m = 0; m < 4; m++){
        float2 a = v[m], b = v[m+4];
        v[m]   = cadd(a, b);
        v[m+4] = cmul(csub(a, b), TWL<DIR>(s_tw, t + 16*m));
    }
    // stage h=32 : pairs (m, m+2) within halves, idx = 2*(t+16*m2)
    #pragma unroll
    for (int g = 0; g < 8; g += 4)
    #pragma unroll
    for (int m2 = 0; m2 < 2; m2++){
        int m = g + m2;
        float2 a = v[m], b = v[m+2];
        v[m]   = cadd(a, b);
        v[m+2] = cmul(csub(a, b), TWL<DIR>(s_tw, 2*(t + 16*m2)));
    }
    // stage h=16 : pairs (m, m+1), idx = 4t
    {
        float2 w = TWL<DIR>(s_tw, 4*t);
        #pragma unroll
        for (int m = 0; m < 8; m += 2){
            float2 a = v[m], b = v[m+1];
            v[m]   = cadd(a, b);
            v[m+1] = cmul(csub(a, b), w);
        }
    }
    // stages h=8,4,2 : cross-lane, idx = (64/h)*(t&(h-1))
    #pragma unroll
    for (int h = 8; h >= 2; h >>= 1){
        float2 w = TWL<DIR>(s_tw, (64/h) * (t & (h-1)));
        const bool hi = (t & h) != 0;
        #pragma unroll
        for (int m = 0; m < 8; m++){
            float ox = __shfl_xor_sync(0xffffffffu, v[m].x, h);
            float oy = __shfl_xor_sync(0xffffffffu, v[m].y, h);
            if (hi) v[m] = cmul(make_float2(ox - v[m].x, oy - v[m].y), w);
            else    v[m] = make_float2(v[m].x + ox, v[m].y + oy);
        }
    }
    // stage h=1 : no twiddle
    {
        const bool hi = (t & 1) != 0;
        #pragma unroll
        for (int m = 0; m < 8; m++){
            float ox = __shfl_xor_sync(0xffffffffu, v[m].x, 1);
            float oy = __shfl_xor_sync(0xffffffffu, v[m].y, 1);
            if (hi) v[m] = make_float2(ox - v[m].x, oy - v[m].y);
            else    v[m] = make_float2(v[m].x + ox, v[m].y + oy);
        }
    }
}

// ============================================================================
// z-axis kernels: fully direct-global (no smem staging).
// 16 lines per 256-thread block; line = blockIdx.x*16 + (tid>>4).
// ============================================================================

// forward: blockIdx.y==0 -> g_wv in place; ==1 -> g_vzr -> g_Vz.
__global__ void __launch_bounds__(256) k_fft_z_fwd(){
    __shared__ float2 s_tw[64];
    fill_tw(s_tw);
    const int t = threadIdx.x & 15;
    const int line = blockIdx.x * 16 + (threadIdx.x >> 4);
    const int base = line * 128;
    float2 v[8];
    if (blockIdx.y == 0){
        #pragma unroll
        for (int m = 0; m < 8; m++) v[m] = g_wv[base + t + 16*m];
    } else {
        #pragma unroll
        for (int m = 0; m < 8; m++) v[m] = make_float2(g_vzr[base + t + 16*m], 0.0f);
    }
    __syncthreads();
    fft128_shfl<-1>(v, t, s_tw);
    const int ko = 8 * rev4(t);
    float4* d4 = (float4*)((blockIdx.y == 0 ? g_wv : g_Vz) + base + ko);
    d4[0] = make_float4(v[0].x, v[0].y, v[4].x, v[4].y);
    d4[1] = make_float4(v[2].x, v[2].y, v[6].x, v[6].y);
    d4[2] = make_float4(v[1].x, v[1].y, v[5].x, v[5].y);
    d4[3] = make_float4(v[3].x, v[3].y, v[7].x, v[7].y);
}

// inverse: g_C -> real g_chi (scaled by 1/128^3).
__global__ void __launch_bounds__(256) k_fft_z_c2r(){
    __shared__ float2 s_tw[64];
    fill_tw(s_tw);
    const int t = threadIdx.x & 15;
    const int line = blockIdx.x * 16 + (threadIdx.x >> 4);
    const int base = line * 128;
    float2 v[8];
    #pragma unroll
    for (int m = 0; m < 8; m++) v[m] = g_C[base + t + 16*m];
    __syncthreads();
    fft128_shfl<1>(v, t, s_tw);
    const float sc = 1.0f / 2097152.0f;
    const int ko = 8 * rev4(t);
    float4* d4 = (float4*)(g_chi + base + ko);
    d4[0] = make_float4(v[0].x*sc, v[4].x*sc, v[2].x*sc, v[6].x*sc);
    d4[1] = make_float4(v[1].x*sc, v[5].x*sc, v[3].x*sc, v[7].x*sc);
}

// ============================================================================
// strided-axis kernels: smem staging tile, 16 z per block.
// ============================================================================

template<int DIR, int WHICH>
__global__ void __launch_bounds__(256) k_fft_strided(int bstride, int estride){
    __shared__ float2 tile[16][129];
    __shared__ float2 s_tw[64];
    fill_tw(s_tw);
    float2* g = (WHICH == 0) ? (blockIdx.z ? g_Vz : g_wv) : g_C;
    const int base = blockIdx.y * bstride + blockIdx.x * 16;
    for (int i = threadIdx.x; i < 2048; i += 256){
        int e = i >> 4, d = i & 15;
        tile[d][SWZ(e)] = g[base + e * estride + d];
    }
    __syncthreads();
    const int t  = threadIdx.x & 15;
    const int ln = threadIdx.x >> 4;
    float2 v[8];
    #pragma unroll
    for (int m = 0; m < 8; m++) v[m] = tile[ln][SWZ(t + 16*m)];
    fft128_shfl<DIR>(v, t, s_tw);
    const int ko = 8 * rev4(t);
    tile[ln][SWZ(ko+0)] = v[0];  tile[ln][SWZ(ko+1)] = v[4];
    tile[ln][SWZ(ko+2)] = v[2];  tile[ln][SWZ(ko+3)] = v[6];
    tile[ln][SWZ(ko+4)] = v[1];  tile[ln][SWZ(ko+5)] = v[5];
    tile[ln][SWZ(ko+6)] = v[3];  tile[ln][SWZ(ko+7)] = v[7];
    __syncthreads();
    for (int i = threadIdx.x; i < 2048; i += 256){
        int e = i >> 4, d = i & 15;
        g[base + e * estride + d] = tile[d][SWZ(e)];
    }
}

// Fused spectral combine + inverse x-pass. ky = blockIdx.y, kz-tile = blockIdx.x*16.
__global__ void __launch_bounds__(256) k_xinv_combine(){
    __shared__ float2 tile[16][129];
    __shared__ float2 s_tw[64];
    fill_tw(s_tw);
    const int ky  = blockIdx.y;
    const int kzb = blockIdx.x * 16;
    const int kym = (128 - ky) & 127;
    const int base = ky * 128 + kzb;
    for (int i = threadIdx.x; i < 2048; i += 256){
        int kx = i >> 4, d = i & 15;
        int kz  = kzb + d;
        int idx = kx * 16384 + base + d;
        int im  = ((128 - kx) & 127) * 16384 + kym * 128 + ((128 - kz) & 127);

        float2 A  = g_wv[idx];
        float2 Bm = g_wv[im];
        float2 Vz = g_Vz[idx];
        // Vx = (A + conj(Bm))/2 ; Vy = -i*(A - conj(Bm))/2
        float2 S = make_float2(A.x + Bm.x, A.y - Bm.y);
        float2 D = make_float2(A.x - Bm.x, A.y + Bm.y);
        float2 Vx = make_float2(0.5f * S.x, 0.5f * S.y);
        float2 Vy = make_float2(0.5f * D.y, -0.5f * D.x);

        float ux = (float)(kx < 64 ? kx : kx - 128);
        float uy = (float)(ky < 64 ? ky : ky - 128);
        float uz = (float)(kz < 64 ? kz : kz - 128);
        float us = ux*ux + uy*uy + uz*uz;
        float gk = __expf(-us * (1.0f / 2048.0f));

        float dre = ux*Vx.x + uy*Vy.x + uz*Vz.x;
        float dim = ux*Vx.y + uy*Vy.y + uz*Vz.y;
        float s = gk / (2.0f * FPI * (us + 1e-6f));
        tile[d][SWZ(kx)] = make_float2(s * dim, -s * dre);
    }
    __syncthreads();
    const int t  = threadIdx.x & 15;
    const int ln = threadIdx.x >> 4;
    float2 v[8];
    #pragma unroll
    for (int m = 0; m < 8; m++) v[m] = tile[ln][SWZ(t + 16*m)];
    fft128_shfl<1>(v, t, s_tw);
    const int ko = 8 * rev4(t);
    tile[ln][SWZ(ko+0)] = v[0];  tile[ln][SWZ(ko+1)] = v[4];
    tile[ln][SWZ(ko+2)] = v[2];  tile[ln][SWZ(ko+3)] = v[6];
    tile[ln][SWZ(ko+4)] = v[1];  tile[ln][SWZ(ko+5)] = v[5];
    tile[ln][SWZ(ko+6)] = v[3];  tile[ln][SWZ(ko+7)] = v[7];
    __syncthreads();
    for (int i = threadIdx.x; i < 2048; i += 256){
        int e = i >> 4, d = i & 15;
        g_C[base + e * 16384 + d] = tile[d][SWZ(e)];
    }
}

// ============================================================================
// Pipeline kernels
// ============================================================================

__global__ void k_init(){
    int i = blockIdx.x * 1024 + threadIdx.x;
    float4 z4 = make_float4(0.f, 0.f, 0.f, 0.f);
    if (i < 1048576) g_b_wv[i] = z4;
    else             g_b_vzr[i - 1048576] = z4;
    if (i < 4)       g_stats[i] = 0.0;
}

__device__ __forceinline__ void corners(float px, float py, float pz,
                                        int ix[2], int iy[2], int iz[2],
                                        float wx[2], float wy[2], float wz[2]){
    float prx = px * 128.0f, pry = py * 128.0f, prz = pz * 128.0f;
    float lox = floorf(prx), loy = floorf(pry), loz = floorf(prz);
    ix[0] = ((int)lox) & 127;  iy[0] = ((int)loy) & 127;  iz[0] = ((int)loz) & 127;
    ix[1] = ((int)ceilf(prx)) & 127;
    iy[1] = ((int)ceilf(pry)) & 127;
    iz[1] = ((int)ceilf(prz)) & 127;
    float fx = prx - lox, fy = pry - loy, fz = prz - loz;
    wx[0] = 1.0f - fx; wx[1] = fx;
    wy[0] = 1.0f - fy; wy[1] = fy;
    wz[0] = 1.0f - fz; wz[1] = fz;
}

__global__ void k_scatter(const float* __restrict__ pts,
                          const float* __restrict__ nrm, int N){
    int n = blockIdx.x * 256 + threadIdx.x;
    if (n >= N) return;
    float px = pts[3*n], py = pts[3*n+1], pz = pts[3*n+2];
    float nx = nrm[3*n], ny = nrm[3*n+1], nz = nrm[3*n+2];
    int ix[2], iy[2], iz[2]; float wx[2], wy[2], wz[2];
    corners(px, py, pz, ix, iy, iz, wx, wy, wz);
    #pragma unroll
    for (int c = 0; c < 8; c++){
        int a = (c >> 2) & 1, b = (c >> 1) & 1, d = c & 1;
        float w = wx[a] * wy[b] * wz[d];
        int idx = (ix[a] << 14) | (iy[b] << 7) | iz[d];
        atomicAdd(&g_wv[idx].x, w * nx);
        atomicAdd(&g_wv[idx].y, w * ny);
        atomicAdd(&g_vzr[idx],  w * nz);
    }
}

__global__ void k_interp(const float* __restrict__ pts, int N){
    int n = blockIdx.x * 256 + threadIdx.x;
    float acc = 0.0f;
    if (n < N){
        float px = pts[3*n], py = pts[3*n+1], pz = pts[3*n+2];
        int ix[2], iy[2], iz[2]; float wx[2], wy[2], wz[2];
        corners(px, py, pz, ix, iy, iz, wx, wy, wz);
        #pragma unroll
        for (int c = 0; c < 8; c++){
            int a = (c >> 2) & 1, b = (c >> 1) & 1, d = c & 1;
            float w = wx[a] * wy[b] * wz[d];
            int idx = (ix[a] << 14) | (iy[b] << 7) | iz[d];
            acc += w * g_chi[idx];
        }
    }
    #pragma unroll
    for (int o = 16; o > 0; o >>= 1)
        acc += __shfl_down_sync(0xffffffffu, acc, o);
    __shared__ float wsum[8];
    if ((threadIdx.x & 31) == 0) wsum[threadIdx.x >> 5] = acc;
    __syncthreads();
    if (threadIdx.x == 0){
        float s = 0.0f;
        #pragma unroll
        for (int i = 0; i < 8; i++) s += wsum[i];
        atomicAdd(&g_stats[0], (double)s);
    }
}

__global__ void k_finalize(int N){
    double mean = g_stats[0] / (double)N;
    double chi0 = (double)g_chi[0] - mean;
    g_stats[1] = mean;
    g_stats[2] = 0.5 / fabs(chi0);
}

__global__ void k_writeout(float4* __restrict__ out){
    int i = blockIdx.x * 256 + threadIdx.x;   // over M3/4
    float mean = (float)g_stats[1];
    float sc   = (float)g_stats[2];
    float4 c = g_b_chi[i];
    out[i] = make_float4(sc*(c.x-mean), sc*(c.y-mean), sc*(c.z-mean), sc*(c.w-mean));
}

// ============================================================================
// launch
// ============================================================================
extern "C" void kernel_launch(void* const* d_in, const int* in_sizes, int n_in,
                              void* d_out, int out_size){
    const float* pts = (const float*)d_in[0];
    const float* nrm = (const float*)d_in[1];
    const int N = in_sizes[0] / 3;

    k_init<<<1536, 1024>>>();
    k_scatter<<<(N + 255) / 256, 256>>>(pts, nrm, N);
    // forward: z (both fields, direct-global), y, x
    k_fft_z_fwd<<<dim3(1024, 2), 256>>>();
    k_fft_strided<-1, 0><<<dim3(8, 128, 2), 256>>>(16384, 128);   // y
    k_fft_strided<-1, 0><<<dim3(8, 128, 2), 256>>>(128, 16384);   // x
    // fused combine + inverse x
    k_xinv_combine<<<dim3(8, 128), 256>>>();
    // inverse: y, then z (direct-global, real out)
    k_fft_strided<1, 1><<<dim3(8, 128, 1), 256>>>(16384, 128);    // y
    k_fft_z_c2r<<<1024, 256>>>();
    // gather, normalize, write
    k_interp<<<(N + 255) / 256, 256>>>(pts, N);
    k_finalize<<<1, 1>>>(N);
    k_writeout<<<2048, 256>>>((float4*)d_out);
}

// round 5
// speedup vs baseline: 1.2149x; 1.0302x over previous
#include <cuda_runtime.h>

// ============================================================================
// DPSR: trilinear scatter -> 3D FFT -> spectral Poisson -> iFFT -> gather/norm
// res = 128, sigma = 2, eps = 1e-6, B = 1, N = 250000, F = 3
//
// Round 5: 8-thread/16-value register FFT. Stages 64/32/16/8 intra-thread,
// one intra-warp swizzled smem exchange (syncwarp only), stages 4/2/1
// intra-thread. Direct sector-efficient global I/O (no staging tiles),
// computed twiddles (1 sincos/thread). Zero shuffles, zero __syncthreads
// in FFT kernels.
// ============================================================================

#define M3   2097152          // 128^3
#define FPI  3.14159265358979f

// ---- scratch (device globals; no allocation allowed) ----
__device__ float4 g_b_wv[M3/2];    // packed vx + i*vy -> W(k)
__device__ float4 g_b_Vz[M3/2];    // spectrum of vz
__device__ float4 g_b_C[M3/2];     // chi_tilde
__device__ float4 g_b_vzr[M3/4];   // scattered vz (real)
__device__ float4 g_b_chi[M3/4];   // chi_prime (real)
__device__ double g_stats[4];

#define g_wv  ((float2*)g_b_wv)
#define g_Vz  ((float2*)g_b_Vz)
#define g_C   ((float2*)g_b_C)
#define g_vzr ((float*)g_b_vzr)
#define g_chi ((float*)g_b_chi)

__device__ __forceinline__ float2 cadd(float2 a, float2 b){ return make_float2(a.x+b.x, a.y+b.y); }
__device__ __forceinline__ float2 csub(float2 a, float2 b){ return make_float2(a.x-b.x, a.y-b.y); }
__device__ __forceinline__ float2 cmul(float2 a, float2 b){
    return make_float2(a.x*b.x - a.y*b.y, a.x*b.y + a.y*b.x);
}

// exchange-buffer swizzle: conflict-free for both p=t+8m and p=16t+j patterns
#define SWX(p) ((p) ^ ((((p) >> 4) & 7)))
#define XPITCH 136

__device__ __forceinline__ int rev3i(int t){
    return ((t & 1) << 2) | (t & 2) | ((t >> 2) & 1);
}

// ============================================================================
// 128-pt radix-2 DIF FFT: 8 threads/line, 16 values/thread (p = t + 8m).
// xrow: this line's 136-float2 exchange row (intra-warp).
// On return v[j] = result at position p = 16t + j; true index
// k = 8*rev4(j) + rev3(t).
// DIR = -1 forward, +1 inverse (unnormalized).
// ============================================================================
template<int DIR>
__device__ __forceinline__ void fft128_16(float2 v[16], const int t,
                                          float2* __restrict__ xrow){
    const float D  = (float)DIR;
    const float SQ = 0.70710678118654752f;
    const float2 c8 = make_float2(0.92387953251128675f, D * 0.38268343236508977f);
    const float2 c4 = make_float2(SQ, D * SQ);

    float s, c;
    __sincosf(D * (FPI / 64.0f) * (float)t, &s, &c);
    const float2 wt  = make_float2(c, s);          // exp(D*i*pi*t/64)
    const float2 w2t = cmul(wt,  wt);
    const float2 w4t = cmul(w2t, w2t);
    const float2 w8t = cmul(w4t, w4t);

    // h=64 : pairs (m, m+8), tw = wt * c8^m
    {
        float2 w = wt;
        #pragma unroll
        for (int m = 0; m < 8; m++){
            float2 a = v[m], b = v[m+8];
            v[m]   = cadd(a, b);
            v[m+8] = cmul(csub(a, b), w);
            w = cmul(w, c8);
        }
    }
    // h=32 : pairs (q, q+4) and (8+q, 12+q), tw = w2t * c4^q
    {
        float2 w = w2t;
        #pragma unroll
        for (int q = 0; q < 4; q++){
            float2 a = v[q],   b = v[q+4];
            v[q]    = cadd(a, b);  v[q+4]  = cmul(csub(a, b), w);
            a = v[8+q]; b = v[12+q];
            v[8+q]  = cadd(a, b);  v[12+q] = cmul(csub(a, b), w);
            w = cmul(w, c4);
        }
    }
    // h=16 : pairs (m, m+2); m even -> w4t, m odd -> w4t*(0,D)
    {
        const float2 wa = w4t;
        const float2 wb = make_float2(-D * w4t.y, D * w4t.x);
        #pragma unroll
        for (int g = 0; g < 16; g += 4){
            float2 a = v[g],   b = v[g+2];
            v[g]   = cadd(a, b);  v[g+2] = cmul(csub(a, b), wa);
            a = v[g+1]; b = v[g+3];
            v[g+1] = cadd(a, b);  v[g+3] = cmul(csub(a, b), wb);
        }
    }
    // h=8 : pairs (m, m+1), tw = w8t
    {
        #pragma unroll
        for (int m = 0; m < 16; m += 2){
            float2 a = v[m], b = v[m+1];
            v[m]   = cadd(a, b);
            v[m+1] = cmul(csub(a, b), w8t);
        }
    }

    // intra-warp exchange: re-own 16 consecutive positions [16t..16t+15]
    #pragma unroll
    for (int m = 0; m < 16; m++) xrow[SWX(t + 8*m)] = v[m];
    __syncwarp();
    #pragma unroll
    for (int j = 0; j < 16; j++) v[j] = xrow[SWX(16*t + j)];

    // h=4 : pairs (j, j+4) in 8-blocks; tw = {1, c4, (0,D), (-SQ, D*SQ)}
    {
        const float2 w2 = make_float2(0.0f, D);
        const float2 w3 = make_float2(-SQ, D * SQ);
        #pragma unroll
        for (int g = 0; g < 16; g += 8){
            float2 a, b;
            a = v[g+0]; b = v[g+4]; v[g+0] = cadd(a,b); v[g+4] = csub(a,b);
            a = v[g+1]; b = v[g+5]; v[g+1] = cadd(a,b); v[g+5] = cmul(csub(a,b), c4);
            a = v[g+2]; b = v[g+6]; v[g+2] = cadd(a,b); v[g+6] = cmul(csub(a,b), w2);
            a = v[g+3]; b = v[g+7]; v[g+3] = cadd(a,b); v[g+7] = cmul(csub(a,b), w3);
        }
    }
    // h=2 : pairs (j, j+2) in 4-blocks; tw = {1, (0,D)}
    {
        #pragma unroll
        for (int g = 0; g < 16; g += 4){
            float2 a, b, d0;
            a = v[g+0]; b = v[g+2]; v[g+0] = cadd(a,b); v[g+2] = csub(a,b);
            a = v[g+1]; b = v[g+3]; v[g+1] = cadd(a,b);
            d0 = csub(a,b);
            v[g+3] = make_float2(-D * d0.y, D * d0.x);
        }
    }
    // h=1
    {
        #pragma unroll
        for (int g = 0; g < 16; g += 2){
            float2 a = v[g], b = v[g+1];
            v[g]   = cadd(a, b);
            v[g+1] = csub(a, b);
        }
    }
}

// store helper: for c=0..15 the output k = 8c + rev3(t) holds v[rev4(c)]
#define REV4(c) ((((c)&1)<<3) | (((c)&2)<<1) | (((c)&4)>>1) | (((c)&8)>>3))

// ============================================================================
// z-axis kernels: lines contiguous in memory. 32 lines per 256-thread block.
// ============================================================================

// forward: blockIdx.y==0 -> g_wv in place; ==1 -> g_vzr (real) -> g_Vz.
__global__ void __launch_bounds__(256) k_fft_z_fwd(){
    __shared__ float2 xch[32][XPITCH];
    const int t    = threadIdx.x & 7;
    const int row  = threadIdx.x >> 3;
    const int base = (blockIdx.x * 32 + row) * 128;
    float2 v[16];
    if (blockIdx.y == 0){
        #pragma unroll
        for (int m = 0; m < 16; m++) v[m] = g_wv[base + t + 8*m];
        fft128_16<-1>(v, t, xch[row]);
        const int rt = rev3i(t);
        #pragma unroll
        for (int c = 0; c < 16; c++) g_wv[base + 8*c + rt] = v[REV4(c)];
    } else {
        #pragma unroll
        for (int m = 0; m < 16; m++) v[m] = make_float2(g_vzr[base + t + 8*m], 0.0f);
        fft128_16<-1>(v, t, xch[row]);
        const int rt = rev3i(t);
        #pragma unroll
        for (int c = 0; c < 16; c++) g_Vz[base + 8*c + rt] = v[REV4(c)];
    }
}

// inverse: g_C -> real g_chi (scaled by 1/128^3)
__global__ void __launch_bounds__(256) k_fft_z_c2r(){
    __shared__ float2 xch[32][XPITCH];
    const int t    = threadIdx.x & 7;
    const int row  = threadIdx.x >> 3;
    const int base = (blockIdx.x * 32 + row) * 128;
    float2 v[16];
    #pragma unroll
    for (int m = 0; m < 16; m++) v[m] = g_C[base + t + 8*m];
    fft128_16<1>(v, t, xch[row]);
    const float sc = 1.0f / 2097152.0f;
    const int rt = rev3i(t);
    #pragma unroll
    for (int c = 0; c < 16; c++) g_chi[base + 8*c + rt] = v[REV4(c)].x * sc;
}

// ============================================================================
// strided-axis kernels: element (e, d) at ybase + e*estride + d.
// 32 d per block (row = tid>>3), direct sector-efficient global I/O.
// WHICH==0: forward fields (blockIdx.z: g_wv / g_Vz); WHICH==1: g_C.
// ============================================================================
template<int DIR, int WHICH>
__global__ void __launch_bounds__(256) k_fft_strided(int bstride, int estride){
    __shared__ float2 xch[32][XPITCH];
    float2* g = (WHICH == 0) ? (blockIdx.z ? g_Vz : g_wv) : g_C;
    const int t    = threadIdx.x & 7;
    const int row  = threadIdx.x >> 3;
    const int obase = blockIdx.y * bstride + blockIdx.x * 32 + row;
    float2 v[16];
    #pragma unroll
    for (int m = 0; m < 16; m++) v[m] = g[obase + (t + 8*m) * estride];
    fft128_16<DIR>(v, t, xch[row]);
    const int rt = rev3i(t);
    #pragma unroll
    for (int c = 0; c < 16; c++) g[obase + (8*c + rt) * estride] = v[REV4(c)];
}

// Fused spectral combine + inverse x-pass. ky = blockIdx.y, kz = blockIdx.x*32+row.
__global__ void __launch_bounds__(256) k_xinv_combine(){
    __shared__ float2 xch[32][XPITCH];
    const int t   = threadIdx.x & 7;
    const int row = threadIdx.x >> 3;
    const int ky  = blockIdx.y;
    const int kz  = blockIdx.x * 32 + row;
    const int kym = (128 - ky) & 127;
    const int kzm = (128 - kz) & 127;
    const float uy = (float)(ky < 64 ? ky : ky - 128);
    const float uz = (float)(kz < 64 ? kz : kz - 128);

    float2 v[16];
    #pragma unroll
    for (int m = 0; m < 16; m++){
        int kx  = t + 8*m;
        int idx = kx * 16384 + ky * 128 + kz;
        int im  = ((128 - kx) & 127) * 16384 + kym * 128 + kzm;

        float2 A  = g_wv[idx];
        float2 Bm = g_wv[im];
        float2 Vz = g_Vz[idx];
        // Vx = (A + conj(Bm))/2 ; Vy = -i*(A - conj(Bm))/2
        float2 Vx = make_float2(0.5f * (A.x + Bm.x), 0.5f * (A.y - Bm.y));
        float2 Vy = make_float2(0.5f * (A.y + Bm.y), -0.5f * (A.x - Bm.x));

        float ux = (float)(kx < 64 ? kx : kx - 128);
        float us = ux*ux + uy*uy + uz*uz;
        float gk = __expf(-us * (1.0f / 2048.0f));

        float dre = ux*Vx.x + uy*Vy.x + uz*Vz.x;
        float dim = ux*Vx.y + uy*Vy.y + uz*Vz.y;
        float s = gk / (2.0f * FPI * (us + 1e-6f));
        v[m] = make_float2(s * dim, -s * dre);
    }
    fft128_16<1>(v, t, xch[row]);
    const int obase = ky * 128 + kz;
    const int rt = rev3i(t);
    #pragma unroll
    for (int c = 0; c < 16; c++) g_C[obase + (8*c + rt) * 16384] = v[REV4(c)];
}

// ============================================================================
// Pipeline kernels
// ============================================================================

__global__ void k_init(){
    int i = blockIdx.x * 1024 + threadIdx.x;
    float4 z4 = make_float4(0.f, 0.f, 0.f, 0.f);
    if (i < 1048576) g_b_wv[i] = z4;
    else             g_b_vzr[i - 1048576] = z4;
    if (i < 4)       g_stats[i] = 0.0;
}

__device__ __forceinline__ void corners(float px, float py, float pz,
                                        int ix[2], int iy[2], int iz[2],
                                        float wx[2], float wy[2], float wz[2]){
    float prx = px * 128.0f, pry = py * 128.0f, prz = pz * 128.0f;
    float lox = floorf(prx), loy = floorf(pry), loz = floorf(prz);
    ix[0] = ((int)lox) & 127;  iy[0] = ((int)loy) & 127;  iz[0] = ((int)loz) & 127;
    ix[1] = ((int)ceilf(prx)) & 127;
    iy[1] = ((int)ceilf(pry)) & 127;
    iz[1] = ((int)ceilf(prz)) & 127;
    float fx = prx - lox, fy = pry - loy, fz = prz - loz;
    wx[0] = 1.0f - fx; wx[1] = fx;
    wy[0] = 1.0f - fy; wy[1] = fy;
    wz[0] = 1.0f - fz; wz[1] = fz;
}

__global__ void k_scatter(const float* __restrict__ pts,
                          const float* __restrict__ nrm, int N){
    int n = blockIdx.x * 256 + threadIdx.x;
    if (n >= N) return;
    float px = pts[3*n], py = pts[3*n+1], pz = pts[3*n+2];
    float nx = nrm[3*n], ny = nrm[3*n+1], nz = nrm[3*n+2];
    int ix[2], iy[2], iz[2]; float wx[2], wy[2], wz[2];
    corners(px, py, pz, ix, iy, iz, wx, wy, wz);
    #pragma unroll
    for (int c = 0; c < 8; c++){
        int a = (c >> 2) & 1, b = (c >> 1) & 1, d = c & 1;
        float w = wx[a] * wy[b] * wz[d];
        int idx = (ix[a] << 14) | (iy[b] << 7) | iz[d];
        atomicAdd(&g_wv[idx].x, w * nx);
        atomicAdd(&g_wv[idx].y, w * ny);
        atomicAdd(&g_vzr[idx],  w * nz);
    }
}

__global__ void k_interp(const float* __restrict__ pts, int N){
    int n = blockIdx.x * 256 + threadIdx.x;
    float acc = 0.0f;
    if (n < N){
        float px = pts[3*n], py = pts[3*n+1], pz = pts[3*n+2];
        int ix[2], iy[2], iz[2]; float wx[2], wy[2], wz[2];
        corners(px, py, pz, ix, iy, iz, wx, wy, wz);
        #pragma unroll
        for (int c = 0; c < 8; c++){
            int a = (c >> 2) & 1, b = (c >> 1) & 1, d = c & 1;
            float w = wx[a] * wy[b] * wz[d];
            int idx = (ix[a] << 14) | (iy[b] << 7) | iz[d];
            acc += w * g_chi[idx];
        }
    }
    #pragma unroll
    for (int o = 16; o > 0; o >>= 1)
        acc += __shfl_down_sync(0xffffffffu, acc, o);
    __shared__ float wsum[8];
    if ((threadIdx.x & 31) == 0) wsum[threadIdx.x >> 5] = acc;
    __syncthreads();
    if (threadIdx.x == 0){
        float s = 0.0f;
        #pragma unroll
        for (int i = 0; i < 8; i++) s += wsum[i];
        atomicAdd(&g_stats[0], (double)s);
    }
}

__global__ void k_finalize(int N){
    double mean = g_stats[0] / (double)N;
    double chi0 = (double)g_chi[0] - mean;
    g_stats[1] = mean;
    g_stats[2] = 0.5 / fabs(chi0);
}

__global__ void k_writeout(float4* __restrict__ out){
    int i = blockIdx.x * 256 + threadIdx.x;   // over M3/4
    float mean = (float)g_stats[1];
    float sc   = (float)g_stats[2];
    float4 c = g_b_chi[i];
    out[i] = make_float4(sc*(c.x-mean), sc*(c.y-mean), sc*(c.z-mean), sc*(c.w-mean));
}

// ============================================================================
// launch
// ============================================================================
extern "C" void kernel_launch(void* const* d_in, const int* in_sizes, int n_in,
                              void* d_out, int out_size){
    const float* pts = (const float*)d_in[0];
    const float* nrm = (const float*)d_in[1];
    const int N = in_sizes[0] / 3;

    k_init<<<1536, 1024>>>();
    k_scatter<<<(N + 255) / 256, 256>>>(pts, nrm, N);
    // forward: z (both fields), y, x
    k_fft_z_fwd<<<dim3(512, 2), 256>>>();
    k_fft_strided<-1, 0><<<dim3(4, 128, 2), 256>>>(16384, 128);   // y
    k_fft_strided<-1, 0><<<dim3(4, 128, 2), 256>>>(128, 16384);   // x
    // fused combine + inverse x
    k_xinv_combine<<<dim3(4, 128), 256>>>();
    // inverse: y, then z (real out)
    k_fft_strided<1, 1><<<dim3(4, 128, 1), 256>>>(16384, 128);    // y
    k_fft_z_c2r<<<512, 256>>>();
    // gather, normalize, write
    k_interp<<<(N + 255) / 256, 256>>>(pts, N);
    k_finalize<<<1, 1>>>(N);
    k_writeout<<<2048, 256>>>((float4*)d_out);
}

// round 6
// speedup vs baseline: 1.2916x; 1.0632x over previous
#include <cuda_runtime.h>

// ============================================================================
// DPSR: trilinear scatter -> 3D FFT -> spectral Poisson -> iFFT -> gather/norm
// res = 128, sigma = 2, eps = 1e-6, B = 1, N = 250000, F = 3
//
// Round 6: plane-fused FFT passes. For each x, the (y,z) plane (128KB) lives
// in dynamic smem: z-FFT + y-FFT with ONE global read + ONE global write.
// Pitch-130 tile + XOR swizzle => conflict-free rows, columns and exchanges.
// ============================================================================

#define M3   2097152          // 128^3
#define FPI  3.14159265358979f
#define TP   130              // tile pitch in float2
#define PLANE_BYTES (128 * TP * sizeof(float2))

// ---- scratch (device globals; no allocation allowed) ----
__device__ float4 g_b_wv[M3/2];    // packed vx + i*vy -> W(k)
__device__ float4 g_b_Vz[M3/2];    // spectrum of vz
__device__ float4 g_b_C[M3/2];     // chi_tilde
__device__ float4 g_b_vzr[M3/4];   // scattered vz (real)
__device__ float4 g_b_chi[M3/4];   // chi_prime (real)
__device__ double g_stats[4];

#define g_wv  ((float2*)g_b_wv)
#define g_Vz  ((float2*)g_b_Vz)
#define g_C   ((float2*)g_b_C)
#define g_vzr ((float*)g_b_vzr)
#define g_chi ((float*)g_b_chi)

__device__ __forceinline__ float2 cadd(float2 a, float2 b){ return make_float2(a.x+b.x, a.y+b.y); }
__device__ __forceinline__ float2 csub(float2 a, float2 b){ return make_float2(a.x-b.x, a.y-b.y); }
__device__ __forceinline__ float2 cmul(float2 a, float2 b){
    return make_float2(a.x*b.x - a.y*b.y, a.x*b.y + a.y*b.x);
}

// exchange swizzle: bijection on [0,128)
#define SWX(p) ((p) ^ ((((p) >> 4) & 7)))
#define XPITCH 136

__device__ __forceinline__ int rev3i(int t){
    return ((t & 1) << 2) | (t & 2) | ((t >> 2) & 1);
}
#define REV4(c) ((((c)&1)<<3) | (((c)&2)<<1) | (((c)&4)>>1) | (((c)&8)>>3))

// ============================================================================
// 128-pt radix-2 DIF FFT: 8 threads/line, 16 values/thread (p = t + 8m).
// Exchange buffer addressed as xbase[SWX(p)*xs] (xs=1: row, xs=TP: column).
// On return v[j] = result at position p = 16t + j; true index
// k = 8*rev4(j) + rev3(t). DIR=-1 fwd, +1 inv (unnormalized).
// Ends with __syncwarp so callers may overwrite the exchange buffer.
// ============================================================================
template<int DIR>
__device__ __forceinline__ void fft128_16(float2 v[16], const int t,
                                          float2* __restrict__ xbase, const int xs){
    const float D  = (float)DIR;
    const float SQ = 0.70710678118654752f;
    const float2 c8 = make_float2(0.92387953251128675f, D * 0.38268343236508977f);
    const float2 c4 = make_float2(SQ, D * SQ);

    float s, c;
    __sincosf(D * (FPI / 64.0f) * (float)t, &s, &c);
    const float2 wt  = make_float2(c, s);
    const float2 w2t = cmul(wt,  wt);
    const float2 w4t = cmul(w2t, w2t);
    const float2 w8t = cmul(w4t, w4t);

    // h=64
    {
        float2 w = wt;
        #pragma unroll
        for (int m = 0; m < 8; m++){
            float2 a = v[m], b = v[m+8];
            v[m]   = cadd(a, b);
            v[m+8] = cmul(csub(a, b), w);
            w = cmul(w, c8);
        }
    }
    // h=32
    {
        float2 w = w2t;
        #pragma unroll
        for (int q = 0; q < 4; q++){
            float2 a = v[q],   b = v[q+4];
            v[q]    = cadd(a, b);  v[q+4]  = cmul(csub(a, b), w);
            a = v[8+q]; b = v[12+q];
            v[8+q]  = cadd(a, b);  v[12+q] = cmul(csub(a, b), w);
            w = cmul(w, c4);
        }
    }
    // h=16
    {
        const float2 wa = w4t;
        const float2 wb = make_float2(-D * w4t.y, D * w4t.x);
        #pragma unroll
        for (int g = 0; g < 16; g += 4){
            float2 a = v[g],   b = v[g+2];
            v[g]   = cadd(a, b);  v[g+2] = cmul(csub(a, b), wa);
            a = v[g+1]; b = v[g+3];
            v[g+1] = cadd(a, b);  v[g+3] = cmul(csub(a, b), wb);
        }
    }
    // h=8
    {
        #pragma unroll
        for (int m = 0; m < 16; m += 2){
            float2 a = v[m], b = v[m+1];
            v[m]   = cadd(a, b);
            v[m+1] = cmul(csub(a, b), w8t);
        }
    }

    // exchange: re-own 16 consecutive positions [16t..16t+15]
    #pragma unroll
    for (int m = 0; m < 16; m++) xbase[SWX(t + 8*m) * xs] = v[m];
    __syncwarp();
    #pragma unroll
    for (int j = 0; j < 16; j++) v[j] = xbase[SWX(16*t + j) * xs];
    __syncwarp();   // callers may overwrite the buffer after return

    // h=4
    {
        const float2 w2 = make_float2(0.0f, D);
        const float2 w3 = make_float2(-SQ, D * SQ);
        #pragma unroll
        for (int g = 0; g < 16; g += 8){
            float2 a, b;
            a = v[g+0]; b = v[g+4]; v[g+0] = cadd(a,b); v[g+4] = csub(a,b);
            a = v[g+1]; b = v[g+5]; v[g+1] = cadd(a,b); v[g+5] = cmul(csub(a,b), c4);
            a = v[g+2]; b = v[g+6]; v[g+2] = cadd(a,b); v[g+6] = cmul(csub(a,b), w2);
            a = v[g+3]; b = v[g+7]; v[g+3] = cadd(a,b); v[g+7] = cmul(csub(a,b), w3);
        }
    }
    // h=2
    {
        #pragma unroll
        for (int g = 0; g < 16; g += 4){
            float2 a, b, d0;
            a = v[g+0]; b = v[g+2]; v[g+0] = cadd(a,b); v[g+2] = csub(a,b);
            a = v[g+1]; b = v[g+3]; v[g+1] = cadd(a,b);
            d0 = csub(a,b);
            v[g+3] = make_float2(-D * d0.y, D * d0.x);
        }
    }
    // h=1
    {
        #pragma unroll
        for (int g = 0; g < 16; g += 2){
            float2 a = v[g], b = v[g+1];
            v[g]   = cadd(a, b);
            v[g+1] = csub(a, b);
        }
    }
}

// ============================================================================
// Plane-fused kernels. 1024 threads = 128 lines of 8 threads.
// Row pass: warp w handles lines {c, c+4, c+8, c+12}, c = (w&3) + 16*(w>>2)
//   -> smem phases pair rows with bank offset delta 16 (pitch 130: 4y mod 32).
// Column pass: warp w handles lines {4w..4w+3} (consecutive)
//   -> banks 4t + 2z, conflict-free.
// ============================================================================

// forward z then y, one field per blockIdx.y (0: g_wv in place, 1: vzr->Vz)
__global__ void __launch_bounds__(1024, 1) k_plane_zy_fwd(){
    extern __shared__ float2 tile[];   // 128 * TP
    const int lane = threadIdx.x & 31;
    const int w    = threadIdx.x >> 5;
    const int t    = lane & 7;
    const int sub  = lane >> 3;
    const int yline = (w & 3) + ((w >> 2) << 4) + (sub << 2);
    const int zline = (w << 2) + sub;
    const int plane = blockIdx.x << 14;

    float2 v[16];
    // ---- z pass (rows, contiguous global) ----
    if (blockIdx.y == 0){
        #pragma unroll
        for (int m = 0; m < 16; m++) v[m] = g_wv[plane + yline*128 + t + 8*m];
    } else {
        #pragma unroll
        for (int m = 0; m < 16; m++) v[m] = make_float2(g_vzr[plane + yline*128 + t + 8*m], 0.0f);
    }
    fft128_16<-1>(v, t, tile + yline*TP, 1);
    {
        const int rt = rev3i(t);
        #pragma unroll
        for (int c = 0; c < 16; c++) tile[yline*TP + 8*c + rt] = v[REV4(c)];
    }
    __syncthreads();
    // ---- y pass (columns) ----
    #pragma unroll
    for (int m = 0; m < 16; m++) v[m] = tile[(t + 8*m)*TP + zline];
    fft128_16<-1>(v, t, tile + zline, TP);
    {
        float2* gout = (blockIdx.y == 0) ? g_wv : g_Vz;
        const int rt = rev3i(t);
        #pragma unroll
        for (int c = 0; c < 16; c++)
            gout[plane + (8*c + rt)*128 + zline] = v[REV4(c)];
    }
}

// inverse z then y on g_C, write real g_chi (scaled 1/128^3)
__global__ void __launch_bounds__(1024, 1) k_plane_yz_inv(){
    extern __shared__ float2 tile[];   // 128 * TP
    const int lane = threadIdx.x & 31;
    const int w    = threadIdx.x >> 5;
    const int t    = lane & 7;
    const int sub  = lane >> 3;
    const int yline = (w & 3) + ((w >> 2) << 4) + (sub << 2);   // ky for row pass
    const int zline = (w << 2) + sub;                            // z for column pass
    const int plane = blockIdx.x << 14;

    float2 v[16];
    // ---- inverse over kz (rows) ----
    #pragma unroll
    for (int m = 0; m < 16; m++) v[m] = g_C[plane + yline*128 + t + 8*m];
    fft128_16<1>(v, t, tile + yline*TP, 1);
    {
        const int rt = rev3i(t);
        #pragma unroll
        for (int c = 0; c < 16; c++) tile[yline*TP + 8*c + rt] = v[REV4(c)];
    }
    __syncthreads();
    // ---- inverse over ky (columns), real output ----
    #pragma unroll
    for (int m = 0; m < 16; m++) v[m] = tile[(t + 8*m)*TP + zline];
    fft128_16<1>(v, t, tile + zline, TP);
    {
        const float sc = 1.0f / 2097152.0f;
        const int rt = rev3i(t);
        #pragma unroll
        for (int c = 0; c < 16; c++)
            g_chi[plane + (8*c + rt)*128 + zline] = v[REV4(c)].x * sc;
    }
}

// ============================================================================
// x-axis strided kernels (unchanged structure)
// ============================================================================

template<int DIR, int WHICH>
__global__ void __launch_bounds__(256) k_fft_strided(int bstride, int estride){
    __shared__ float2 xch[32][XPITCH];
    float2* g = (WHICH == 0) ? (blockIdx.z ? g_Vz : g_wv) : g_C;
    const int t    = threadIdx.x & 7;
    const int row  = threadIdx.x >> 3;
    const int obase = blockIdx.y * bstride + blockIdx.x * 32 + row;
    float2 v[16];
    #pragma unroll
    for (int m = 0; m < 16; m++) v[m] = g[obase + (t + 8*m) * estride];
    fft128_16<DIR>(v, t, xch[row], 1);
    const int rt = rev3i(t);
    #pragma unroll
    for (int c = 0; c < 16; c++) g[obase + (8*c + rt) * estride] = v[REV4(c)];
}

// Fused spectral combine + inverse x-pass. ky = blockIdx.y, kz = blockIdx.x*32+row.
__global__ void __launch_bounds__(256) k_xinv_combine(){
    __shared__ float2 xch[32][XPITCH];
    const int t   = threadIdx.x & 7;
    const int row = threadIdx.x >> 3;
    const int ky  = blockIdx.y;
    const int kz  = blockIdx.x * 32 + row;
    const int kym = (128 - ky) & 127;
    const int kzm = (128 - kz) & 127;
    const float uy = (float)(ky < 64 ? ky : ky - 128);
    const float uz = (float)(kz < 64 ? kz : kz - 128);

    float2 v[16];
    #pragma unroll
    for (int m = 0; m < 16; m++){
        int kx  = t + 8*m;
        int idx = kx * 16384 + ky * 128 + kz;
        int im  = ((128 - kx) & 127) * 16384 + kym * 128 + kzm;

        float2 A  = g_wv[idx];
        float2 Bm = g_wv[im];
        float2 Vz = g_Vz[idx];
        float2 Vx = make_float2(0.5f * (A.x + Bm.x), 0.5f * (A.y - Bm.y));
        float2 Vy = make_float2(0.5f * (A.y + Bm.y), -0.5f * (A.x - Bm.x));

        float ux = (float)(kx < 64 ? kx : kx - 128);
        float us = ux*ux + uy*uy + uz*uz;
        float gk = __expf(-us * (1.0f / 2048.0f));

        float dre = ux*Vx.x + uy*Vy.x + uz*Vz.x;
        float dim = ux*Vx.y + uy*Vy.y + uz*Vz.y;
        float s = gk / (2.0f * FPI * (us + 1e-6f));
        v[m] = make_float2(s * dim, -s * dre);
    }
    fft128_16<1>(v, t, xch[row], 1);
    const int obase = ky * 128 + kz;
    const int rt = rev3i(t);
    #pragma unroll
    for (int c = 0; c < 16; c++) g_C[obase + (8*c + rt) * 16384] = v[REV4(c)];
}

// ============================================================================
// Pipeline kernels
// ============================================================================

__global__ void k_init(){
    int i = blockIdx.x * 1024 + threadIdx.x;
    float4 z4 = make_float4(0.f, 0.f, 0.f, 0.f);
    if (i < 1048576) g_b_wv[i] = z4;
    else             g_b_vzr[i - 1048576] = z4;
    if (i < 4)       g_stats[i] = 0.0;
}

__device__ __forceinline__ void corners(float px, float py, float pz,
                                        int ix[2], int iy[2], int iz[2],
                                        float wx[2], float wy[2], float wz[2]){
    float prx = px * 128.0f, pry = py * 128.0f, prz = pz * 128.0f;
    float lox = floorf(prx), loy = floorf(pry), loz = floorf(prz);
    ix[0] = ((int)lox) & 127;  iy[0] = ((int)loy) & 127;  iz[0] = ((int)loz) & 127;
    ix[1] = ((int)ceilf(prx)) & 127;
    iy[1] = ((int)ceilf(pry)) & 127;
    iz[1] = ((int)ceilf(prz)) & 127;
    float fx = prx - lox, fy = pry - loy, fz = prz - loz;
    wx[0] = 1.0f - fx; wx[1] = fx;
    wy[0] = 1.0f - fy; wy[1] = fy;
    wz[0] = 1.0f - fz; wz[1] = fz;
}

__global__ void k_scatter(const float* __restrict__ pts,
                          const float* __restrict__ nrm, int N){
    int n = blockIdx.x * 256 + threadIdx.x;
    if (n >= N) return;
    float px = pts[3*n], py = pts[3*n+1], pz = pts[3*n+2];
    float nx = nrm[3*n], ny = nrm[3*n+1], nz = nrm[3*n+2];
    int ix[2], iy[2], iz[2]; float wx[2], wy[2], wz[2];
    corners(px, py, pz, ix, iy, iz, wx, wy, wz);
    #pragma unroll
    for (int c = 0; c < 8; c++){
        int a = (c >> 2) & 1, b = (c >> 1) & 1, d = c & 1;
        float w = wx[a] * wy[b] * wz[d];
        int idx = (ix[a] << 14) | (iy[b] << 7) | iz[d];
        atomicAdd(&g_wv[idx].x, w * nx);
        atomicAdd(&g_wv[idx].y, w * ny);
        atomicAdd(&g_vzr[idx],  w * nz);
    }
}

__global__ void k_interp(const float* __restrict__ pts, int N){
    int n = blockIdx.x * 256 + threadIdx.x;
    float acc = 0.0f;
    if (n < N){
        float px = pts[3*n], py = pts[3*n+1], pz = pts[3*n+2];
        int ix[2], iy[2], iz[2]; float wx[2], wy[2], wz[2];
        corners(px, py, pz, ix, iy, iz, wx, wy, wz);
        #pragma unroll
        for (int c = 0; c < 8; c++){
            int a = (c >> 2) & 1, b = (c >> 1) & 1, d = c & 1;
            float w = wx[a] * wy[b] * wz[d];
            int idx = (ix[a] << 14) | (iy[b] << 7) | iz[d];
            acc += w * g_chi[idx];
        }
    }
    #pragma unroll
    for (int o = 16; o > 0; o >>= 1)
        acc += __shfl_down_sync(0xffffffffu, acc, o);
    __shared__ float wsum[8];
    if ((threadIdx.x & 31) == 0) wsum[threadIdx.x >> 5] = acc;
    __syncthreads();
    if (threadIdx.x == 0){
        float s = 0.0f;
        #pragma unroll
        for (int i = 0; i < 8; i++) s += wsum[i];
        atomicAdd(&g_stats[0], (double)s);
    }
}

__global__ void k_finalize(int N){
    double mean = g_stats[0] / (double)N;
    double chi0 = (double)g_chi[0] - mean;
    g_stats[1] = mean;
    g_stats[2] = 0.5 / fabs(chi0);
}

__global__ void k_writeout(float4* __restrict__ out){
    int i = blockIdx.x * 256 + threadIdx.x;   // over M3/4
    float mean = (float)g_stats[1];
    float sc   = (float)g_stats[2];
    float4 c = g_b_chi[i];
    out[i] = make_float4(sc*(c.x-mean), sc*(c.y-mean), sc*(c.z-mean), sc*(c.w-mean));
}

// ============================================================================
// launch
// ============================================================================
extern "C" void kernel_launch(void* const* d_in, const int* in_sizes, int n_in,
                              void* d_out, int out_size){
    const float* pts = (const float*)d_in[0];
    const float* nrm = (const float*)d_in[1];
    const int N = in_sizes[0] / 3;

    // allow 130KB dynamic smem on the plane kernels (idempotent)
    cudaFuncSetAttribute(k_plane_zy_fwd, cudaFuncAttributeMaxDynamicSharedMemorySize,
                         (int)PLANE_BYTES);
    cudaFuncSetAttribute(k_plane_yz_inv, cudaFuncAttributeMaxDynamicSharedMemorySize,
                         (int)PLANE_BYTES);

    k_init<<<1536, 1024>>>();
    k_scatter<<<(N + 255) / 256, 256>>>(pts, nrm, N);
    // forward: fused z+y per plane (both fields), then x strided
    k_plane_zy_fwd<<<dim3(128, 2), 1024, PLANE_BYTES>>>();
    k_fft_strided<-1, 0><<<dim3(4, 128, 2), 256>>>(128, 16384);   // x
    // fused combine + inverse x
    k_xinv_combine<<<dim3(4, 128), 256>>>();
    // inverse: fused kz+ky per plane, real output
    k_plane_yz_inv<<<128, 1024, PLANE_BYTES>>>();
    // gather, normalize, write
    k_interp<<<(N + 255) / 256, 256>>>(pts, N);
    k_finalize<<<1, 1>>>(N);
    k_writeout<<<2048, 256>>>((float4*)d_out);
}

// round 7
// speedup vs baseline: 1.3422x; 1.0392x over previous
#include <cuda_runtime.h>

// ============================================================================
// DPSR: trilinear scatter -> 3D FFT -> spectral Poisson -> iFFT -> gather/norm
// res = 128, sigma = 2, eps = 1e-6, B = 1, N = 250000, F = 3
//
// Round 7: single fused x-phase kernel: fwd x-FFT (own wv + Hermitian-mirror
// wv + vz) + spectral combine + inverse x-FFT, one global read set, one
// global write (g_C). Plane-fused z+y passes unchanged from round 6.
// ============================================================================

#define M3   2097152          // 128^3
#define FPI  3.14159265358979f
#define TP   130              // plane tile pitch in float2
#define PLANE_BYTES (128 * TP * sizeof(float2))

// ---- scratch (device globals; no allocation allowed) ----
__device__ float4 g_b_wv[M3/2];    // packed vx + i*vy (zy-transformed)
__device__ float4 g_b_Vz[M3/2];    // vz (zy-transformed)
__device__ float4 g_b_C[M3/2];     // chi_tilde (x-inverse applied)
__device__ float4 g_b_vzr[M3/4];   // scattered vz (real)
__device__ float4 g_b_chi[M3/4];   // chi_prime (real)
__device__ double g_stats[4];

#define g_wv  ((float2*)g_b_wv)
#define g_Vz  ((float2*)g_b_Vz)
#define g_C   ((float2*)g_b_C)
#define g_vzr ((float*)g_b_vzr)
#define g_chi ((float*)g_b_chi)

__device__ __forceinline__ float2 cadd(float2 a, float2 b){ return make_float2(a.x+b.x, a.y+b.y); }
__device__ __forceinline__ float2 csub(float2 a, float2 b){ return make_float2(a.x-b.x, a.y-b.y); }
__device__ __forceinline__ float2 cmul(float2 a, float2 b){
    return make_float2(a.x*b.x - a.y*b.y, a.x*b.y + a.y*b.x);
}

#define SWX(p) ((p) ^ ((((p) >> 4) & 7)))
#define XPITCH 136

__device__ __forceinline__ int rev3i(int t){
    return ((t & 1) << 2) | (t & 2) | ((t >> 2) & 1);
}
#define REV4(c) ((((c)&1)<<3) | (((c)&2)<<1) | (((c)&4)>>1) | (((c)&8)>>3))

// ============================================================================
// 128-pt radix-2 DIF FFT: 8 threads/line, 16 values/thread (p = t + 8m).
// Exchange buffer: xbase[SWX(p)*xs]. On return v[j] = result at p = 16t+j;
// true index k = 8*rev4(j)+rev3(t). Ends with __syncwarp (buffer reusable).
// ============================================================================
template<int DIR>
__device__ __forceinline__ void fft128_16(float2 v[16], const int t,
                                          float2* __restrict__ xbase, const int xs){
    const float D  = (float)DIR;
    const float SQ = 0.70710678118654752f;
    const float2 c8 = make_float2(0.92387953251128675f, D * 0.38268343236508977f);
    const float2 c4 = make_float2(SQ, D * SQ);

    float s, c;
    __sincosf(D * (FPI / 64.0f) * (float)t, &s, &c);
    const float2 wt  = make_float2(c, s);
    const float2 w2t = cmul(wt,  wt);
    const float2 w4t = cmul(w2t, w2t);
    const float2 w8t = cmul(w4t, w4t);

    // h=64
    {
        float2 w = wt;
        #pragma unroll
        for (int m = 0; m < 8; m++){
            float2 a = v[m], b = v[m+8];
            v[m]   = cadd(a, b);
            v[m+8] = cmul(csub(a, b), w);
            w = cmul(w, c8);
        }
    }
    // h=32
    {
        float2 w = w2t;
        #pragma unroll
        for (int q = 0; q < 4; q++){
            float2 a = v[q],   b = v[q+4];
            v[q]    = cadd(a, b);  v[q+4]  = cmul(csub(a, b), w);
            a = v[8+q]; b = v[12+q];
            v[8+q]  = cadd(a, b);  v[12+q] = cmul(csub(a, b), w);
            w = cmul(w, c4);
        }
    }
    // h=16
    {
        const float2 wa = w4t;
        const float2 wb = make_float2(-D * w4t.y, D * w4t.x);
        #pragma unroll
        for (int g = 0; g < 16; g += 4){
            float2 a = v[g],   b = v[g+2];
            v[g]   = cadd(a, b);  v[g+2] = cmul(csub(a, b), wa);
            a = v[g+1]; b = v[g+3];
            v[g+1] = cadd(a, b);  v[g+3] = cmul(csub(a, b), wb);
        }
    }
    // h=8
    {
        #pragma unroll
        for (int m = 0; m < 16; m += 2){
            float2 a = v[m], b = v[m+1];
            v[m]   = cadd(a, b);
            v[m+1] = cmul(csub(a, b), w8t);
        }
    }

    // exchange: re-own 16 consecutive positions [16t..16t+15]
    #pragma unroll
    for (int m = 0; m < 16; m++) xbase[SWX(t + 8*m) * xs] = v[m];
    __syncwarp();
    #pragma unroll
    for (int j = 0; j < 16; j++) v[j] = xbase[SWX(16*t + j) * xs];
    __syncwarp();   // callers may overwrite the buffer after return

    // h=4
    {
        const float2 w2 = make_float2(0.0f, D);
        const float2 w3 = make_float2(-SQ, D * SQ);
        #pragma unroll
        for (int g = 0; g < 16; g += 8){
            float2 a, b;
            a = v[g+0]; b = v[g+4]; v[g+0] = cadd(a,b); v[g+4] = csub(a,b);
            a = v[g+1]; b = v[g+5]; v[g+1] = cadd(a,b); v[g+5] = cmul(csub(a,b), c4);
            a = v[g+2]; b = v[g+6]; v[g+2] = cadd(a,b); v[g+6] = cmul(csub(a,b), w2);
            a = v[g+3]; b = v[g+7]; v[g+3] = cadd(a,b); v[g+7] = cmul(csub(a,b), w3);
        }
    }
    // h=2
    {
        #pragma unroll
        for (int g = 0; g < 16; g += 4){
            float2 a, b, d0;
            a = v[g+0]; b = v[g+2]; v[g+0] = cadd(a,b); v[g+2] = csub(a,b);
            a = v[g+1]; b = v[g+3]; v[g+1] = cadd(a,b);
            d0 = csub(a,b);
            v[g+3] = make_float2(-D * d0.y, D * d0.x);
        }
    }
    // h=1
    {
        #pragma unroll
        for (int g = 0; g < 16; g += 2){
            float2 a = v[g], b = v[g+1];
            v[g]   = cadd(a, b);
            v[g+1] = csub(a, b);
        }
    }
}

// ============================================================================
// Plane-fused z+y kernels (unchanged from round 6).
// ============================================================================

__global__ void __launch_bounds__(1024, 1) k_plane_zy_fwd(){
    extern __shared__ float2 tile[];   // 128 * TP
    const int lane = threadIdx.x & 31;
    const int w    = threadIdx.x >> 5;
    const int t    = lane & 7;
    const int sub  = lane >> 3;
    const int yline = (w & 3) + ((w >> 2) << 4) + (sub << 2);
    const int zline = (w << 2) + sub;
    const int plane = blockIdx.x << 14;

    float2 v[16];
    if (blockIdx.y == 0){
        #pragma unroll
        for (int m = 0; m < 16; m++) v[m] = g_wv[plane + yline*128 + t + 8*m];
    } else {
        #pragma unroll
        for (int m = 0; m < 16; m++) v[m] = make_float2(g_vzr[plane + yline*128 + t + 8*m], 0.0f);
    }
    fft128_16<-1>(v, t, tile + yline*TP, 1);
    {
        const int rt = rev3i(t);
        #pragma unroll
        for (int c = 0; c < 16; c++) tile[yline*TP + 8*c + rt] = v[REV4(c)];
    }
    __syncthreads();
    #pragma unroll
    for (int m = 0; m < 16; m++) v[m] = tile[(t + 8*m)*TP + zline];
    fft128_16<-1>(v, t, tile + zline, TP);
    {
        float2* gout = (blockIdx.y == 0) ? g_wv : g_Vz;
        const int rt = rev3i(t);
        #pragma unroll
        for (int c = 0; c < 16; c++)
            gout[plane + (8*c + rt)*128 + zline] = v[REV4(c)];
    }
}

__global__ void __launch_bounds__(1024, 1) k_plane_yz_inv(){
    extern __shared__ float2 tile[];   // 128 * TP
    const int lane = threadIdx.x & 31;
    const int w    = threadIdx.x >> 5;
    const int t    = lane & 7;
    const int sub  = lane >> 3;
    const int yline = (w & 3) + ((w >> 2) << 4) + (sub << 2);
    const int zline = (w << 2) + sub;
    const int plane = blockIdx.x << 14;

    float2 v[16];
    #pragma unroll
    for (int m = 0; m < 16; m++) v[m] = g_C[plane + yline*128 + t + 8*m];
    fft128_16<1>(v, t, tile + yline*TP, 1);
    {
        const int rt = rev3i(t);
        #pragma unroll
        for (int c = 0; c < 16; c++) tile[yline*TP + 8*c + rt] = v[REV4(c)];
    }
    __syncthreads();
    #pragma unroll
    for (int m = 0; m < 16; m++) v[m] = tile[(t + 8*m)*TP + zline];
    fft128_16<1>(v, t, tile + zline, TP);
    {
        const float sc = 1.0f / 2097152.0f;
        const int rt = rev3i(t);
        #pragma unroll
        for (int c = 0; c < 16; c++)
            g_chi[plane + (8*c + rt)*128 + zline] = v[REV4(c)].x * sc;
    }
}

// ============================================================================
// Fused x-phase: fwd FFT (mirror wv, own wv, vz) + combine + inverse x-FFT.
// Block: 256 threads = 32 rows (kz) x 8 threads. ky = blockIdx.y,
// kz = blockIdx.x*32 + row. Writes g_C only.
// ============================================================================
__global__ void __launch_bounds__(256) k_x_fused(){
    __shared__ float2 xch [32][XPITCH];
    __shared__ float2 sMir[32][TP];
    const int t    = threadIdx.x & 7;
    const int row  = threadIdx.x >> 3;
    const int rt   = rev3i(t);
    const int ky   = blockIdx.y;
    const int kz   = blockIdx.x * 32 + row;
    const int obase = ky * 128 + kz;
    const int mbase = ((128 - ky) & 127) * 128 + ((128 - kz) & 127);
    const float uy = (float)(ky < 64 ? ky : ky - 128);
    const float uz = (float)(kz < 64 ? kz : kz - 128);

    float2 v[16];

    // (a) mirror wv line: forward FFT -> sMir[row][k]  (L2-hot redundant read)
    #pragma unroll
    for (int m = 0; m < 16; m++) v[m] = g_wv[mbase + (t + 8*m) * 16384];
    fft128_16<-1>(v, t, xch[row], 1);
    #pragma unroll
    for (int c = 0; c < 16; c++) sMir[row][8*c + rt] = v[REV4(c)];

    // (b) own wv line: forward FFT -> regs
    #pragma unroll
    for (int m = 0; m < 16; m++) v[m] = g_wv[obase + (t + 8*m) * 16384];
    fft128_16<-1>(v, t, xch[row], 1);
    __syncwarp();

    // (c) partial combine (ux,uy terms): A own, Bm mirror from smem
    #pragma unroll
    for (int j = 0; j < 16; j++){
        const int k = 8 * REV4(j) + rt;
        float2 A  = v[j];
        float2 Bm = sMir[row][(128 - k) & 127];
        // Vx = (A + conj(Bm))/2 ; Vy = -i*(A - conj(Bm))/2
        float2 Vx = make_float2(0.5f * (A.x + Bm.x), 0.5f * (A.y - Bm.y));
        float2 Vy = make_float2(0.5f * (A.y + Bm.y), -0.5f * (A.x - Bm.x));
        float ux = (float)(k < 64 ? k : k - 128);
        float us = ux*ux + uy*uy + uz*uz;
        float gk = __expf(-us * (1.0f / 2048.0f));
        float s  = gk / (2.0f * FPI * (us + 1e-6f));
        float dre = ux*Vx.x + uy*Vy.x;
        float dim = ux*Vx.y + uy*Vy.y;
        v[j] = make_float2(s * dim, -s * dre);   // (-i)*(dre+i*dim)*s
    }
    __syncwarp();   // all mirror reads done before overwriting sMir
    #pragma unroll
    for (int c = 0; c < 16; c++) sMir[row][8*c + rt] = v[REV4(c)];  // park partial at k

    // (d) vz line: forward FFT -> regs
    #pragma unroll
    for (int m = 0; m < 16; m++) v[m] = g_Vz[obase + (t + 8*m) * 16384];
    fft128_16<-1>(v, t, xch[row], 1);
    __syncwarp();

    // (e) final combine: chi(k) = partial(k) + s*uz*(-i*Vz)
    #pragma unroll
    for (int j = 0; j < 16; j++){
        const int k = 8 * REV4(j) + rt;
        float2 P  = sMir[row][k];
        float2 Vz = v[j];
        float ux = (float)(k < 64 ? k : k - 128);
        float us = ux*ux + uy*uy + uz*uz;
        float gk = __expf(-us * (1.0f / 2048.0f));
        float s  = gk / (2.0f * FPI * (us + 1e-6f));
        v[j] = make_float2(P.x + s * uz * Vz.y, P.y - s * uz * Vz.x);
    }

    // (f) reorder chi from k-order to position order via xch
    #pragma unroll
    for (int c = 0; c < 16; c++) xch[row][8*c + rt] = v[REV4(c)];
    __syncwarp();
    #pragma unroll
    for (int m = 0; m < 16; m++) v[m] = xch[row][t + 8*m];
    __syncwarp();

    // (g) inverse FFT along x, write g_C
    fft128_16<1>(v, t, xch[row], 1);
    #pragma unroll
    for (int c = 0; c < 16; c++) g_C[obase + (8*c + rt) * 16384] = v[REV4(c)];
}

// ============================================================================
// Pipeline kernels
// ============================================================================

__global__ void k_init(){
    int i = blockIdx.x * 1024 + threadIdx.x;
    float4 z4 = make_float4(0.f, 0.f, 0.f, 0.f);
    if (i < 1048576) g_b_wv[i] = z4;
    else             g_b_vzr[i - 1048576] = z4;
    if (i < 4)       g_stats[i] = 0.0;
}

__device__ __forceinline__ void corners(float px, float py, float pz,
                                        int ix[2], int iy[2], int iz[2],
                                        float wx[2], float wy[2], float wz[2]){
    float prx = px * 128.0f, pry = py * 128.0f, prz = pz * 128.0f;
    float lox = floorf(prx), loy = floorf(pry), loz = floorf(prz);
    ix[0] = ((int)lox) & 127;  iy[0] = ((int)loy) & 127;  iz[0] = ((int)loz) & 127;
    ix[1] = ((int)ceilf(prx)) & 127;
    iy[1] = ((int)ceilf(pry)) & 127;
    iz[1] = ((int)ceilf(prz)) & 127;
    float fx = prx - lox, fy = pry - loy, fz = prz - loz;
    wx[0] = 1.0f - fx; wx[1] = fx;
    wy[0] = 1.0f - fy; wy[1] = fy;
    wz[0] = 1.0f - fz; wz[1] = fz;
}

__global__ void k_scatter(const float* __restrict__ pts,
                          const float* __restrict__ nrm, int N){
    int n = blockIdx.x * 256 + threadIdx.x;
    if (n >= N) return;
    float px = pts[3*n], py = pts[3*n+1], pz = pts[3*n+2];
    float nx = nrm[3*n], ny = nrm[3*n+1], nz = nrm[3*n+2];
    int ix[2], iy[2], iz[2]; float wx[2], wy[2], wz[2];
    corners(px, py, pz, ix, iy, iz, wx, wy, wz);
    #pragma unroll
    for (int c = 0; c < 8; c++){
        int a = (c >> 2) & 1, b = (c >> 1) & 1, d = c & 1;
        float w = wx[a] * wy[b] * wz[d];
        int idx = (ix[a] << 14) | (iy[b] << 7) | iz[d];
        atomicAdd(&g_wv[idx].x, w * nx);
        atomicAdd(&g_wv[idx].y, w * ny);
        atomicAdd(&g_vzr[idx],  w * nz);
    }
}

__global__ void k_interp(const float* __restrict__ pts, int N){
    int n = blockIdx.x * 256 + threadIdx.x;
    float acc = 0.0f;
    if (n < N){
        float px = pts[3*n], py = pts[3*n+1], pz = pts[3*n+2];
        int ix[2], iy[2], iz[2]; float wx[2], wy[2], wz[2];
        corners(px, py, pz, ix, iy, iz, wx, wy, wz);
        #pragma unroll
        for (int c = 0; c < 8; c++){
            int a = (c >> 2) & 1, b = (c >> 1) & 1, d = c & 1;
            float w = wx[a] * wy[b] * wz[d];
            int idx = (ix[a] << 14) | (iy[b] << 7) | iz[d];
            acc += w * g_chi[idx];
        }
    }
    #pragma unroll
    for (int o = 16; o > 0; o >>= 1)
        acc += __shfl_down_sync(0xffffffffu, acc, o);
    __shared__ float wsum[8];
    if ((threadIdx.x & 31) == 0) wsum[threadIdx.x >> 5] = acc;
    __syncthreads();
    if (threadIdx.x == 0){
        float s = 0.0f;
        #pragma unroll
        for (int i = 0; i < 8; i++) s += wsum[i];
        atomicAdd(&g_stats[0], (double)s);
    }
}

__global__ void k_finalize(int N){
    double mean = g_stats[0] / (double)N;
    double chi0 = (double)g_chi[0] - mean;
    g_stats[1] = mean;
    g_stats[2] = 0.5 / fabs(chi0);
}

__global__ void k_writeout(float4* __restrict__ out){
    int i = blockIdx.x * 256 + threadIdx.x;   // over M3/4
    float mean = (float)g_stats[1];
    float sc   = (float)g_stats[2];
    float4 c = g_b_chi[i];
    out[i] = make_float4(sc*(c.x-mean), sc*(c.y-mean), sc*(c.z-mean), sc*(c.w-mean));
}

// ============================================================================
// launch
// ============================================================================
extern "C" void kernel_launch(void* const* d_in, const int* in_sizes, int n_in,
                              void* d_out, int out_size){
    const float* pts = (const float*)d_in[0];
    const float* nrm = (const float*)d_in[1];
    const int N = in_sizes[0] / 3;

    cudaFuncSetAttribute(k_plane_zy_fwd, cudaFuncAttributeMaxDynamicSharedMemorySize,
                         (int)PLANE_BYTES);
    cudaFuncSetAttribute(k_plane_yz_inv, cudaFuncAttributeMaxDynamicSharedMemorySize,
                         (int)PLANE_BYTES);

    k_init<<<1536, 1024>>>();
    k_scatter<<<(N + 255) / 256, 256>>>(pts, nrm, N);
    // forward: fused z+y per plane (both fields)
    k_plane_zy_fwd<<<dim3(128, 2), 1024, PLANE_BYTES>>>();
    // fused x-phase: fwd x (wv own+mirror, vz) + combine + inverse x
    k_x_fused<<<dim3(4, 128), 256>>>();
    // inverse: fused kz+ky per plane, real output
    k_plane_yz_inv<<<128, 1024, PLANE_BYTES>>>();
    // gather, normalize, write
    k_interp<<<(N + 255) / 256, 256>>>(pts, N);
    k_finalize<<<1, 1>>>(N);
    k_writeout<<<2048, 256>>>((float4*)d_out);
}

// round 8
// speedup vs baseline: 1.3847x; 1.0317x over previous
#include <cuda_runtime.h>

// ============================================================================
// DPSR: trilinear scatter -> 3D FFT -> spectral Poisson -> iFFT -> gather/norm
// res = 128, sigma = 2, eps = 1e-6, B = 1, N = 250000, F = 3
//
// Round 8: k_x_fused occupancy fix — __launch_bounds__(256,2) (128-reg cap,
// 2 blocks/SM) + spectral scale cached in smem (kills 2nd expf/div chain).
// ============================================================================

#define M3   2097152          // 128^3
#define FPI  3.14159265358979f
#define TP   130              // plane tile pitch in float2
#define PLANE_BYTES (128 * TP * sizeof(float2))

// ---- scratch (device globals; no allocation allowed) ----
__device__ float4 g_b_wv[M3/2];    // packed vx + i*vy (zy-transformed)
__device__ float4 g_b_Vz[M3/2];    // vz (zy-transformed)
__device__ float4 g_b_C[M3/2];     // chi_tilde (x-inverse applied)
__device__ float4 g_b_vzr[M3/4];   // scattered vz (real)
__device__ float4 g_b_chi[M3/4];   // chi_prime (real)
__device__ double g_stats[4];

#define g_wv  ((float2*)g_b_wv)
#define g_Vz  ((float2*)g_b_Vz)
#define g_C   ((float2*)g_b_C)
#define g_vzr ((float*)g_b_vzr)
#define g_chi ((float*)g_b_chi)

__device__ __forceinline__ float2 cadd(float2 a, float2 b){ return make_float2(a.x+b.x, a.y+b.y); }
__device__ __forceinline__ float2 csub(float2 a, float2 b){ return make_float2(a.x-b.x, a.y-b.y); }
__device__ __forceinline__ float2 cmul(float2 a, float2 b){
    return make_float2(a.x*b.x - a.y*b.y, a.x*b.y + a.y*b.x);
}

#define SWX(p) ((p) ^ ((((p) >> 4) & 7)))
#define XPITCH 136

__device__ __forceinline__ int rev3i(int t){
    return ((t & 1) << 2) | (t & 2) | ((t >> 2) & 1);
}
#define REV4(c) ((((c)&1)<<3) | (((c)&2)<<1) | (((c)&4)>>1) | (((c)&8)>>3))

// ============================================================================
// 128-pt radix-2 DIF FFT: 8 threads/line, 16 values/thread (p = t + 8m).
// Exchange buffer: xbase[SWX(p)*xs]. On return v[j] = result at p = 16t+j;
// true index k = 8*rev4(j)+rev3(t). Ends with __syncwarp (buffer reusable).
// ============================================================================
template<int DIR>
__device__ __forceinline__ void fft128_16(float2 v[16], const int t,
                                          float2* __restrict__ xbase, const int xs){
    const float D  = (float)DIR;
    const float SQ = 0.70710678118654752f;
    const float2 c8 = make_float2(0.92387953251128675f, D * 0.38268343236508977f);
    const float2 c4 = make_float2(SQ, D * SQ);

    float s, c;
    __sincosf(D * (FPI / 64.0f) * (float)t, &s, &c);
    const float2 wt  = make_float2(c, s);
    const float2 w2t = cmul(wt,  wt);
    const float2 w4t = cmul(w2t, w2t);
    const float2 w8t = cmul(w4t, w4t);

    // h=64
    {
        float2 w = wt;
        #pragma unroll
        for (int m = 0; m < 8; m++){
            float2 a = v[m], b = v[m+8];
            v[m]   = cadd(a, b);
            v[m+8] = cmul(csub(a, b), w);
            w = cmul(w, c8);
        }
    }
    // h=32
    {
        float2 w = w2t;
        #pragma unroll
        for (int q = 0; q < 4; q++){
            float2 a = v[q],   b = v[q+4];
            v[q]    = cadd(a, b);  v[q+4]  = cmul(csub(a, b), w);
            a = v[8+q]; b = v[12+q];
            v[8+q]  = cadd(a, b);  v[12+q] = cmul(csub(a, b), w);
            w = cmul(w, c4);
        }
    }
    // h=16
    {
        const float2 wa = w4t;
        const float2 wb = make_float2(-D * w4t.y, D * w4t.x);
        #pragma unroll
        for (int g = 0; g < 16; g += 4){
            float2 a = v[g],   b = v[g+2];
            v[g]   = cadd(a, b);  v[g+2] = cmul(csub(a, b), wa);
            a = v[g+1]; b = v[g+3];
            v[g+1] = cadd(a, b);  v[g+3] = cmul(csub(a, b), wb);
        }
    }
    // h=8
    {
        #pragma unroll
        for (int m = 0; m < 16; m += 2){
            float2 a = v[m], b = v[m+1];
            v[m]   = cadd(a, b);
            v[m+1] = cmul(csub(a, b), w8t);
        }
    }

    // exchange: re-own 16 consecutive positions [16t..16t+15]
    #pragma unroll
    for (int m = 0; m < 16; m++) xbase[SWX(t + 8*m) * xs] = v[m];
    __syncwarp();
    #pragma unroll
    for (int j = 0; j < 16; j++) v[j] = xbase[SWX(16*t + j) * xs];
    __syncwarp();   // callers may overwrite the buffer after return

    // h=4
    {
        const float2 w2 = make_float2(0.0f, D);
        const float2 w3 = make_float2(-SQ, D * SQ);
        #pragma unroll
        for (int g = 0; g < 16; g += 8){
            float2 a, b;
            a = v[g+0]; b = v[g+4]; v[g+0] = cadd(a,b); v[g+4] = csub(a,b);
            a = v[g+1]; b = v[g+5]; v[g+1] = cadd(a,b); v[g+5] = cmul(csub(a,b), c4);
            a = v[g+2]; b = v[g+6]; v[g+2] = cadd(a,b); v[g+6] = cmul(csub(a,b), w2);
            a = v[g+3]; b = v[g+7]; v[g+3] = cadd(a,b); v[g+7] = cmul(csub(a,b), w3);
        }
    }
    // h=2
    {
        #pragma unroll
        for (int g = 0; g < 16; g += 4){
            float2 a, b, d0;
            a = v[g+0]; b = v[g+2]; v[g+0] = cadd(a,b); v[g+2] = csub(a,b);
            a = v[g+1]; b = v[g+3]; v[g+1] = cadd(a,b);
            d0 = csub(a,b);
            v[g+3] = make_float2(-D * d0.y, D * d0.x);
        }
    }
    // h=1
    {
        #pragma unroll
        for (int g = 0; g < 16; g += 2){
            float2 a = v[g], b = v[g+1];
            v[g]   = cadd(a, b);
            v[g+1] = csub(a, b);
        }
    }
}

// ============================================================================
// Plane-fused z+y kernels.
// ============================================================================

__global__ void __launch_bounds__(1024, 1) k_plane_zy_fwd(){
    extern __shared__ float2 tile[];   // 128 * TP
    const int lane = threadIdx.x & 31;
    const int w    = threadIdx.x >> 5;
    const int t    = lane & 7;
    const int sub  = lane >> 3;
    const int yline = (w & 3) + ((w >> 2) << 4) + (sub << 2);
    const int zline = (w << 2) + sub;
    const int plane = blockIdx.x << 14;

    float2 v[16];
    if (blockIdx.y == 0){
        #pragma unroll
        for (int m = 0; m < 16; m++) v[m] = g_wv[plane + yline*128 + t + 8*m];
    } else {
        #pragma unroll
        for (int m = 0; m < 16; m++) v[m] = make_float2(g_vzr[plane + yline*128 + t + 8*m], 0.0f);
    }
    fft128_16<-1>(v, t, tile + yline*TP, 1);
    {
        const int rt = rev3i(t);
        #pragma unroll
        for (int c = 0; c < 16; c++) tile[yline*TP + 8*c + rt] = v[REV4(c)];
    }
    __syncthreads();
    #pragma unroll
    for (int m = 0; m < 16; m++) v[m] = tile[(t + 8*m)*TP + zline];
    fft128_16<-1>(v, t, tile + zline, TP);
    {
        float2* gout = (blockIdx.y == 0) ? g_wv : g_Vz;
        const int rt = rev3i(t);
        #pragma unroll
        for (int c = 0; c < 16; c++)
            gout[plane + (8*c + rt)*128 + zline] = v[REV4(c)];
    }
}

__global__ void __launch_bounds__(1024, 1) k_plane_yz_inv(){
    extern __shared__ float2 tile[];   // 128 * TP
    const int lane = threadIdx.x & 31;
    const int w    = threadIdx.x >> 5;
    const int t    = lane & 7;
    const int sub  = lane >> 3;
    const int yline = (w & 3) + ((w >> 2) << 4) + (sub << 2);
    const int zline = (w << 2) + sub;
    const int plane = blockIdx.x << 14;

    float2 v[16];
    #pragma unroll
    for (int m = 0; m < 16; m++) v[m] = g_C[plane + yline*128 + t + 8*m];
    fft128_16<1>(v, t, tile + yline*TP, 1);
    {
        const int rt = rev3i(t);
        #pragma unroll
        for (int c = 0; c < 16; c++) tile[yline*TP + 8*c + rt] = v[REV4(c)];
    }
    __syncthreads();
    #pragma unroll
    for (int m = 0; m < 16; m++) v[m] = tile[(t + 8*m)*TP + zline];
    fft128_16<1>(v, t, tile + zline, TP);
    {
        const float sc = 1.0f / 2097152.0f;
        const int rt = rev3i(t);
        #pragma unroll
        for (int c = 0; c < 16; c++)
            g_chi[plane + (8*c + rt)*128 + zline] = v[REV4(c)].x * sc;
    }
}

// ============================================================================
// Fused x-phase: fwd FFT (mirror wv, own wv, vz) + combine + inverse x-FFT.
// 256 threads = 32 rows (kz) x 8 threads. __launch_bounds__(256,2) caps
// regs at 128 -> 2 blocks/SM. Spectral scale cached in sS during partial
// combine, reused in final combine (no 2nd expf/div chain).
// ============================================================================
__global__ void __launch_bounds__(256, 2) k_x_fused(){
    __shared__ float2 xch [32][XPITCH];
    __shared__ float2 sMir[32][TP];
    __shared__ float  sS  [32][128];
    const int t    = threadIdx.x & 7;
    const int row  = threadIdx.x >> 3;
    const int rt   = rev3i(t);
    const int ky   = blockIdx.y;
    const int kz   = blockIdx.x * 32 + row;
    const int obase = ky * 128 + kz;
    const int mbase = ((128 - ky) & 127) * 128 + ((128 - kz) & 127);
    const float uy = (float)(ky < 64 ? ky : ky - 128);
    const float uz = (float)(kz < 64 ? kz : kz - 128);

    float2 v[16];

    // (a) mirror wv line: forward FFT -> sMir[row][k]  (L2-hot redundant read)
    #pragma unroll
    for (int m = 0; m < 16; m++) v[m] = g_wv[mbase + (t + 8*m) * 16384];
    fft128_16<-1>(v, t, xch[row], 1);
    #pragma unroll
    for (int c = 0; c < 16; c++) sMir[row][8*c + rt] = v[REV4(c)];

    // (b) own wv line: forward FFT -> regs
    #pragma unroll
    for (int m = 0; m < 16; m++) v[m] = g_wv[obase + (t + 8*m) * 16384];
    fft128_16<-1>(v, t, xch[row], 1);
    __syncwarp();

    // (c) partial combine (ux,uy terms); cache scale s in sS
    #pragma unroll
    for (int j = 0; j < 16; j++){
        const int k = 8 * REV4(j) + rt;
        float2 A  = v[j];
        float2 Bm = sMir[row][(128 - k) & 127];
        // Vx = (A + conj(Bm))/2 ; Vy = -i*(A - conj(Bm))/2
        float2 Vx = make_float2(0.5f * (A.x + Bm.x), 0.5f * (A.y - Bm.y));
        float2 Vy = make_float2(0.5f * (A.y + Bm.y), -0.5f * (A.x - Bm.x));
        float ux = (float)(k < 64 ? k : k - 128);
        float us = ux*ux + uy*uy + uz*uz;
        float gk = __expf(-us * (1.0f / 2048.0f));
        float s  = gk / (2.0f * FPI * (us + 1e-6f));
        sS[row][k] = s;
        float dre = ux*Vx.x + uy*Vy.x;
        float dim = ux*Vx.y + uy*Vy.y;
        v[j] = make_float2(s * dim, -s * dre);   // (-i)*(dre+i*dim)*s
    }
    __syncwarp();   // all mirror reads done before overwriting sMir
    #pragma unroll
    for (int c = 0; c < 16; c++) sMir[row][8*c + rt] = v[REV4(c)];  // park partial at k

    // (d) vz line: forward FFT -> regs
    #pragma unroll
    for (int m = 0; m < 16; m++) v[m] = g_Vz[obase + (t + 8*m) * 16384];
    fft128_16<-1>(v, t, xch[row], 1);
    __syncwarp();

    // (e) final combine: chi(k) = partial(k) + s*uz*(-i*Vz)
    #pragma unroll
    for (int j = 0; j < 16; j++){
        const int k = 8 * REV4(j) + rt;
        float2 P   = sMir[row][k];
        float  suz = sS[row][k] * uz;
        float2 Vz  = v[j];
        v[j] = make_float2(P.x + suz * Vz.y, P.y - suz * Vz.x);
    }

    // (f) reorder chi from k-order to position order via xch
    #pragma unroll
    for (int c = 0; c < 16; c++) xch[row][8*c + rt] = v[REV4(c)];
    __syncwarp();
    #pragma unroll
    for (int m = 0; m < 16; m++) v[m] = xch[row][t + 8*m];
    __syncwarp();

    // (g) inverse FFT along x, write g_C
    fft128_16<1>(v, t, xch[row], 1);
    #pragma unroll
    for (int c = 0; c < 16; c++) g_C[obase + (8*c + rt) * 16384] = v[REV4(c)];
}

// ============================================================================
// Pipeline kernels
// ============================================================================

__global__ void k_init(){
    int i = blockIdx.x * 1024 + threadIdx.x;
    float4 z4 = make_float4(0.f, 0.f, 0.f, 0.f);
    if (i < 1048576) g_b_wv[i] = z4;
    else             g_b_vzr[i - 1048576] = z4;
    if (i < 4)       g_stats[i] = 0.0;
}

__device__ __forceinline__ void corners(float px, float py, float pz,
                                        int ix[2], int iy[2], int iz[2],
                                        float wx[2], float wy[2], float wz[2]){
    float prx = px * 128.0f, pry = py * 128.0f, prz = pz * 128.0f;
    float lox = floorf(prx), loy = floorf(pry), loz = floorf(prz);
    ix[0] = ((int)lox) & 127;  iy[0] = ((int)loy) & 127;  iz[0] = ((int)loz) & 127;
    ix[1] = ((int)ceilf(prx)) & 127;
    iy[1] = ((int)ceilf(pry)) & 127;
    iz[1] = ((int)ceilf(prz)) & 127;
    float fx = prx - lox, fy = pry - loy, fz = prz - loz;
    wx[0] = 1.0f - fx; wx[1] = fx;
    wy[0] = 1.0f - fy; wy[1] = fy;
    wz[0] = 1.0f - fz; wz[1] = fz;
}

__global__ void k_scatter(const float* __restrict__ pts,
                          const float* __restrict__ nrm, int N){
    int n = blockIdx.x * 256 + threadIdx.x;
    if (n >= N) return;
    float px = pts[3*n], py = pts[3*n+1], pz = pts[3*n+2];
    float nx = nrm[3*n], ny = nrm[3*n+1], nz = nrm[3*n+2];
    int ix[2], iy[2], iz[2]; float wx[2], wy[2], wz[2];
    corners(px, py, pz, ix, iy, iz, wx, wy, wz);
    #pragma unroll
    for (int c = 0; c < 8; c++){
        int a = (c >> 2) & 1, b = (c >> 1) & 1, d = c & 1;
        float w = wx[a] * wy[b] * wz[d];
        int idx = (ix[a] << 14) | (iy[b] << 7) | iz[d];
        atomicAdd(&g_wv[idx].x, w * nx);
        atomicAdd(&g_wv[idx].y, w * ny);
        atomicAdd(&g_vzr[idx],  w * nz);
    }
}

__global__ void k_interp(const float* __restrict__ pts, int N){
    int n = blockIdx.x * 256 + threadIdx.x;
    float acc = 0.0f;
    if (n < N){
        float px = pts[3*n], py = pts[3*n+1], pz = pts[3*n+2];
        int ix[2], iy[2], iz[2]; float wx[2], wy[2], wz[2];
        corners(px, py, pz, ix, iy, iz, wx, wy, wz);
        #pragma unroll
        for (int c = 0; c < 8; c++){
            int a = (c >> 2) & 1, b = (c >> 1) & 1, d = c & 1;
            float w = wx[a] * wy[b] * wz[d];
            int idx = (ix[a] << 14) | (iy[b] << 7) | iz[d];
            acc += w * g_chi[idx];
        }
    }
    #pragma unroll
    for (int o = 16; o > 0; o >>= 1)
        acc += __shfl_down_sync(0xffffffffu, acc, o);
    __shared__ float wsum[8];
    if ((threadIdx.x & 31) == 0) wsum[threadIdx.x >> 5] = acc;
    __syncthreads();
    if (threadIdx.x == 0){
        float s = 0.0f;
        #pragma unroll
        for (int i = 0; i < 8; i++) s += wsum[i];
        atomicAdd(&g_stats[0], (double)s);
    }
}

__global__ void k_finalize(int N){
    double mean = g_stats[0] / (double)N;
    double chi0 = (double)g_chi[0] - mean;
    g_stats[1] = mean;
    g_stats[2] = 0.5 / fabs(chi0);
}

__global__ void k_writeout(float4* __restrict__ out){
    int i = blockIdx.x * 256 + threadIdx.x;   // over M3/4
    float mean = (float)g_stats[1];
    float sc   = (float)g_stats[2];
    float4 c = g_b_chi[i];
    out[i] = make_float4(sc*(c.x-mean), sc*(c.y-mean), sc*(c.z-mean), sc*(c.w-mean));
}

// ============================================================================
// launch
// ============================================================================
extern "C" void kernel_launch(void* const* d_in, const int* in_sizes, int n_in,
                              void* d_out, int out_size){
    const float* pts = (const float*)d_in[0];
    const float* nrm = (const float*)d_in[1];
    const int N = in_sizes[0] / 3;

    cudaFuncSetAttribute(k_plane_zy_fwd, cudaFuncAttributeMaxDynamicSharedMemorySize,
                         (int)PLANE_BYTES);
    cudaFuncSetAttribute(k_plane_yz_inv, cudaFuncAttributeMaxDynamicSharedMemorySize,
                         (int)PLANE_BYTES);

    k_init<<<1536, 1024>>>();
    k_scatter<<<(N + 255) / 256, 256>>>(pts, nrm, N);
    // forward: fused z+y per plane (both fields)
    k_plane_zy_fwd<<<dim3(128, 2), 1024, PLANE_BYTES>>>();
    // fused x-phase: fwd x (wv own+mirror, vz) + combine + inverse x
    k_x_fused<<<dim3(4, 128), 256>>>();
    // inverse: fused kz+ky per plane, real output
    k_plane_yz_inv<<<128, 1024, PLANE_BYTES>>>();
    // gather, normalize, write
    k_interp<<<(N + 255) / 256, 256>>>(pts, N);
    k_finalize<<<1, 1>>>(N);
    k_writeout<<<2048, 256>>>((float4*)d_out);
}

// round 9
// speedup vs baseline: 1.4405x; 1.0403x over previous
#include <cuda_runtime.h>

// ============================================================================
// DPSR: trilinear scatter -> 3D FFT -> spectral Poisson -> iFFT -> gather/norm
// res = 128, sigma = 2, eps = 1e-6, B = 1, N = 250000, F = 3
//
// Round 9: mirror-paired x-phase — each block holds a line AND its Hermitian
// partner (row^16), sharing forward spectra through smem. Removes the
// redundant mirror FFT (96 FFTs / 64 line-reads per 32 outputs, was 128/96).
// ============================================================================

#define M3   2097152          // 128^3
#define FPI  3.14159265358979f
#define TP   130              // plane tile pitch in float2
#define PLANE_BYTES (128 * TP * sizeof(float2))

// ---- scratch (device globals; no allocation allowed) ----
__device__ float4 g_b_wv[M3/2];    // packed vx + i*vy (zy-transformed)
__device__ float4 g_b_Vz[M3/2];    // vz (zy-transformed)
__device__ float4 g_b_C[M3/2];     // chi_tilde (x-inverse applied)
__device__ float4 g_b_vzr[M3/4];   // scattered vz (real)
__device__ float4 g_b_chi[M3/4];   // chi_prime (real)
__device__ double g_stats[4];

#define g_wv  ((float2*)g_b_wv)
#define g_Vz  ((float2*)g_b_Vz)
#define g_C   ((float2*)g_b_C)
#define g_vzr ((float*)g_b_vzr)
#define g_chi ((float*)g_b_chi)

__device__ __forceinline__ float2 cadd(float2 a, float2 b){ return make_float2(a.x+b.x, a.y+b.y); }
__device__ __forceinline__ float2 csub(float2 a, float2 b){ return make_float2(a.x-b.x, a.y-b.y); }
__device__ __forceinline__ float2 cmul(float2 a, float2 b){
    return make_float2(a.x*b.x - a.y*b.y, a.x*b.y + a.y*b.x);
}

#define SWX(p) ((p) ^ ((((p) >> 4) & 7)))
#define XPITCH 136

__device__ __forceinline__ int rev3i(int t){
    return ((t & 1) << 2) | (t & 2) | ((t >> 2) & 1);
}
#define REV4(c) ((((c)&1)<<3) | (((c)&2)<<1) | (((c)&4)>>1) | (((c)&8)>>3))

// ============================================================================
// 128-pt radix-2 DIF FFT: 8 threads/line, 16 values/thread (p = t + 8m).
// Exchange buffer: xbase[SWX(p)*xs]. On return v[j] = result at p = 16t+j;
// true index k = 8*rev4(j)+rev3(t). Ends with __syncwarp (buffer reusable).
// ============================================================================
template<int DIR>
__device__ __forceinline__ void fft128_16(float2 v[16], const int t,
                                          float2* __restrict__ xbase, const int xs){
    const float D  = (float)DIR;
    const float SQ = 0.70710678118654752f;
    const float2 c8 = make_float2(0.92387953251128675f, D * 0.38268343236508977f);
    const float2 c4 = make_float2(SQ, D * SQ);

    float s, c;
    __sincosf(D * (FPI / 64.0f) * (float)t, &s, &c);
    const float2 wt  = make_float2(c, s);
    const float2 w2t = cmul(wt,  wt);
    const float2 w4t = cmul(w2t, w2t);
    const float2 w8t = cmul(w4t, w4t);

    // h=64
    {
        float2 w = wt;
        #pragma unroll
        for (int m = 0; m < 8; m++){
            float2 a = v[m], b = v[m+8];
            v[m]   = cadd(a, b);
            v[m+8] = cmul(csub(a, b), w);
            w = cmul(w, c8);
        }
    }
    // h=32
    {
        float2 w = w2t;
        #pragma unroll
        for (int q = 0; q < 4; q++){
            float2 a = v[q],   b = v[q+4];
            v[q]    = cadd(a, b);  v[q+4]  = cmul(csub(a, b), w);
            a = v[8+q]; b = v[12+q];
            v[8+q]  = cadd(a, b);  v[12+q] = cmul(csub(a, b), w);
            w = cmul(w, c4);
        }
    }
    // h=16
    {
        const float2 wa = w4t;
        const float2 wb = make_float2(-D * w4t.y, D * w4t.x);
        #pragma unroll
        for (int g = 0; g < 16; g += 4){
            float2 a = v[g],   b = v[g+2];
            v[g]   = cadd(a, b);  v[g+2] = cmul(csub(a, b), wa);
            a = v[g+1]; b = v[g+3];
            v[g+1] = cadd(a, b);  v[g+3] = cmul(csub(a, b), wb);
        }
    }
    // h=8
    {
        #pragma unroll
        for (int m = 0; m < 16; m += 2){
            float2 a = v[m], b = v[m+1];
            v[m]   = cadd(a, b);
            v[m+1] = cmul(csub(a, b), w8t);
        }
    }

    // exchange: re-own 16 consecutive positions [16t..16t+15]
    #pragma unroll
    for (int m = 0; m < 16; m++) xbase[SWX(t + 8*m) * xs] = v[m];
    __syncwarp();
    #pragma unroll
    for (int j = 0; j < 16; j++) v[j] = xbase[SWX(16*t + j) * xs];
    __syncwarp();   // callers may overwrite the buffer after return

    // h=4
    {
        const float2 w2 = make_float2(0.0f, D);
        const float2 w3 = make_float2(-SQ, D * SQ);
        #pragma unroll
        for (int g = 0; g < 16; g += 8){
            float2 a, b;
            a = v[g+0]; b = v[g+4]; v[g+0] = cadd(a,b); v[g+4] = csub(a,b);
            a = v[g+1]; b = v[g+5]; v[g+1] = cadd(a,b); v[g+5] = cmul(csub(a,b), c4);
            a = v[g+2]; b = v[g+6]; v[g+2] = cadd(a,b); v[g+6] = cmul(csub(a,b), w2);
            a = v[g+3]; b = v[g+7]; v[g+3] = cadd(a,b); v[g+7] = cmul(csub(a,b), w3);
        }
    }
    // h=2
    {
        #pragma unroll
        for (int g = 0; g < 16; g += 4){
            float2 a, b, d0;
            a = v[g+0]; b = v[g+2]; v[g+0] = cadd(a,b); v[g+2] = csub(a,b);
            a = v[g+1]; b = v[g+3]; v[g+1] = cadd(a,b);
            d0 = csub(a,b);
            v[g+3] = make_float2(-D * d0.y, D * d0.x);
        }
    }
    // h=1
    {
        #pragma unroll
        for (int g = 0; g < 16; g += 2){
            float2 a = v[g], b = v[g+1];
            v[g]   = cadd(a, b);
            v[g+1] = csub(a, b);
        }
    }
}

// ============================================================================
// Plane-fused z+y kernels (unchanged).
// ============================================================================

__global__ void __launch_bounds__(1024, 1) k_plane_zy_fwd(){
    extern __shared__ float2 tile[];   // 128 * TP
    const int lane = threadIdx.x & 31;
    const int w    = threadIdx.x >> 5;
    const int t    = lane & 7;
    const int sub  = lane >> 3;
    const int yline = (w & 3) + ((w >> 2) << 4) + (sub << 2);
    const int zline = (w << 2) + sub;
    const int plane = blockIdx.x << 14;

    float2 v[16];
    if (blockIdx.y == 0){
        #pragma unroll
        for (int m = 0; m < 16; m++) v[m] = g_wv[plane + yline*128 + t + 8*m];
    } else {
        #pragma unroll
        for (int m = 0; m < 16; m++) v[m] = make_float2(g_vzr[plane + yline*128 + t + 8*m], 0.0f);
    }
    fft128_16<-1>(v, t, tile + yline*TP, 1);
    {
        const int rt = rev3i(t);
        #pragma unroll
        for (int c = 0; c < 16; c++) tile[yline*TP + 8*c + rt] = v[REV4(c)];
    }
    __syncthreads();
    #pragma unroll
    for (int m = 0; m < 16; m++) v[m] = tile[(t + 8*m)*TP + zline];
    fft128_16<-1>(v, t, tile + zline, TP);
    {
        float2* gout = (blockIdx.y == 0) ? g_wv : g_Vz;
        const int rt = rev3i(t);
        #pragma unroll
        for (int c = 0; c < 16; c++)
            gout[plane + (8*c + rt)*128 + zline] = v[REV4(c)];
    }
}

__global__ void __launch_bounds__(1024, 1) k_plane_yz_inv(){
    extern __shared__ float2 tile[];   // 128 * TP
    const int lane = threadIdx.x & 31;
    const int w    = threadIdx.x >> 5;
    const int t    = lane & 7;
    const int sub  = lane >> 3;
    const int yline = (w & 3) + ((w >> 2) << 4) + (sub << 2);
    const int zline = (w << 2) + sub;
    const int plane = blockIdx.x << 14;

    float2 v[16];
    #pragma unroll
    for (int m = 0; m < 16; m++) v[m] = g_C[plane + yline*128 + t + 8*m];
    fft128_16<1>(v, t, tile + yline*TP, 1);
    {
        const int rt = rev3i(t);
        #pragma unroll
        for (int c = 0; c < 16; c++) tile[yline*TP + 8*c + rt] = v[REV4(c)];
    }
    __syncthreads();
    #pragma unroll
    for (int m = 0; m < 16; m++) v[m] = tile[(t + 8*m)*TP + zline];
    fft128_16<1>(v, t, tile + zline, TP);
    {
        const float sc = 1.0f / 2097152.0f;
        const int rt = rev3i(t);
        #pragma unroll
        for (int c = 0; c < 16; c++)
            g_chi[plane + (8*c + rt)*128 + zline] = v[REV4(c)].x * sc;
    }
}

// ============================================================================
// Mirror-paired fused x-phase. 256 threads = 32 rows x 8 threads.
// Rows 0..15: lines (kyA, kz = 16*blockIdx.x + r); rows 16..31: Hermitian
// partners ((128-kyA)&127, (128-kz)&127). partner(row) = row^16.
// Per row: fwd wv FFT -> sW; combine (own + partner spectra) -> partial;
// park partial in sW; fwd vz FFT; final combine; inverse FFT -> g_C.
// kyA = blockIdx.y in [0,64]; ky 0 and 64 self-pair (benign duplicate work).
// ============================================================================
__global__ void __launch_bounds__(256, 2) k_x_fused(){
    __shared__ float2 xch[32][XPITCH];
    __shared__ float2 sW [32][XPITCH];
    __shared__ float  sS [32][XPITCH];
    const int t    = threadIdx.x & 7;
    const int row  = threadIdx.x >> 3;
    const int rt   = rev3i(t);
    const int r    = row & 15;
    const bool isB = row >= 16;
    const int kyA  = blockIdx.y;
    const int kzA  = blockIdx.x * 16 + r;
    const int ky   = isB ? ((128 - kyA) & 127) : kyA;
    const int kz   = isB ? ((128 - kzA) & 127) : kzA;
    const int obase = ky * 128 + kz;
    const float uy = (float)(ky < 64 ? ky : ky - 128);
    const float uz = (float)(kz < 64 ? kz : kz - 128);

    float2 v[16];

    // (a) own wv line: forward FFT -> sW[row][k]
    #pragma unroll
    for (int m = 0; m < 16; m++) v[m] = g_wv[obase + (t + 8*m) * 16384];
    fft128_16<-1>(v, t, xch[row], 1);
    #pragma unroll
    for (int c = 0; c < 16; c++) sW[row][8*c + rt] = v[REV4(c)];
    __syncthreads();

    // (b) partial combine (ux,uy terms): A = own spectrum (regs hold it in
    //     position order? no — re-read from sW is avoided: v still holds own
    //     spectrum with v[j] at k=8*REV4(j)+rt). Bm from partner row.
    #pragma unroll
    for (int j = 0; j < 16; j++){
        const int k = 8 * REV4(j) + rt;
        float2 A  = v[j];
        float2 Bm = sW[row ^ 16][(128 - k) & 127];
        // Vx = (A + conj(Bm))/2 ; Vy = -i*(A - conj(Bm))/2
        float2 Vx = make_float2(0.5f * (A.x + Bm.x), 0.5f * (A.y - Bm.y));
        float2 Vy = make_float2(0.5f * (A.y + Bm.y), -0.5f * (A.x - Bm.x));
        float ux = (float)(k < 64 ? k : k - 128);
        float us = ux*ux + uy*uy + uz*uz;
        float gk = __expf(-us * (1.0f / 2048.0f));
        float s  = gk / (2.0f * FPI * (us + 1e-6f));
        sS[row][k] = s;
        float dre = ux*Vx.x + uy*Vy.x;
        float dim = ux*Vx.y + uy*Vy.y;
        v[j] = make_float2(s * dim, -s * dre);   // (-i)*(dre+i*dim)*s
    }
    __syncthreads();   // all partner reads done before overwriting sW

    // (c) park partial chi at k-order in own sW row
    #pragma unroll
    for (int c = 0; c < 16; c++) sW[row][8*c + rt] = v[REV4(c)];

    // (d) vz line: forward FFT -> regs
    #pragma unroll
    for (int m = 0; m < 16; m++) v[m] = g_Vz[obase + (t + 8*m) * 16384];
    fft128_16<-1>(v, t, xch[row], 1);
    __syncwarp();

    // (e) final combine: chi(k) = partial(k) + s*uz*(-i*Vz)
    #pragma unroll
    for (int j = 0; j < 16; j++){
        const int k = 8 * REV4(j) + rt;
        float2 P   = sW[row][k];
        float  suz = sS[row][k] * uz;
        float2 Vz  = v[j];
        v[j] = make_float2(P.x + suz * Vz.y, P.y - suz * Vz.x);
    }

    // (f) reorder chi from k-order to position order via xch
    #pragma unroll
    for (int c = 0; c < 16; c++) xch[row][8*c + rt] = v[REV4(c)];
    __syncwarp();
    #pragma unroll
    for (int m = 0; m < 16; m++) v[m] = xch[row][t + 8*m];
    __syncwarp();

    // (g) inverse FFT along x, write g_C
    fft128_16<1>(v, t, xch[row], 1);
    #pragma unroll
    for (int c = 0; c < 16; c++) g_C[obase + (8*c + rt) * 16384] = v[REV4(c)];
}

// ============================================================================
// Pipeline kernels
// ============================================================================

__global__ void k_init(){
    int i = blockIdx.x * 1024 + threadIdx.x;
    float4 z4 = make_float4(0.f, 0.f, 0.f, 0.f);
    if (i < 1048576) g_b_wv[i] = z4;
    else             g_b_vzr[i - 1048576] = z4;
    if (i < 4)       g_stats[i] = 0.0;
}

__device__ __forceinline__ void corners(float px, float py, float pz,
                                        int ix[2], int iy[2], int iz[2],
                                        float wx[2], float wy[2], float wz[2]){
    float prx = px * 128.0f, pry = py * 128.0f, prz = pz * 128.0f;
    float lox = floorf(prx), loy = floorf(pry), loz = floorf(prz);
    ix[0] = ((int)lox) & 127;  iy[0] = ((int)loy) & 127;  iz[0] = ((int)loz) & 127;
    ix[1] = ((int)ceilf(prx)) & 127;
    iy[1] = ((int)ceilf(pry)) & 127;
    iz[1] = ((int)ceilf(prz)) & 127;
    float fx = prx - lox, fy = pry - loy, fz = prz - loz;
    wx[0] = 1.0f - fx; wx[1] = fx;
    wy[0] = 1.0f - fy; wy[1] = fy;
    wz[0] = 1.0f - fz; wz[1] = fz;
}

__global__ void k_scatter(const float* __restrict__ pts,
                          const float* __restrict__ nrm, int N){
    int n = blockIdx.x * 256 + threadIdx.x;
    if (n >= N) return;
    float px = pts[3*n], py = pts[3*n+1], pz = pts[3*n+2];
    float nx = nrm[3*n], ny = nrm[3*n+1], nz = nrm[3*n+2];
    int ix[2], iy[2], iz[2]; float wx[2], wy[2], wz[2];
    corners(px, py, pz, ix, iy, iz, wx, wy, wz);
    #pragma unroll
    for (int c = 0; c < 8; c++){
        int a = (c >> 2) & 1, b = (c >> 1) & 1, d = c & 1;
        float w = wx[a] * wy[b] * wz[d];
        int idx = (ix[a] << 14) | (iy[b] << 7) | iz[d];
        atomicAdd(&g_wv[idx].x, w * nx);
        atomicAdd(&g_wv[idx].y, w * ny);
        atomicAdd(&g_vzr[idx],  w * nz);
    }
}

__global__ void k_interp(const float* __restrict__ pts, int N){
    int n = blockIdx.x * 256 + threadIdx.x;
    float acc = 0.0f;
    if (n < N){
        float px = pts[3*n], py = pts[3*n+1], pz = pts[3*n+2];
        int ix[2], iy[2], iz[2]; float wx[2], wy[2], wz[2];
        corners(px, py, pz, ix, iy, iz, wx, wy, wz);
        #pragma unroll
        for (int c = 0; c < 8; c++){
            int a = (c >> 2) & 1, b = (c >> 1) & 1, d = c & 1;
            float w = wx[a] * wy[b] * wz[d];
            int idx = (ix[a] << 14) | (iy[b] << 7) | iz[d];
            acc += w * g_chi[idx];
        }
    }
    #pragma unroll
    for (int o = 16; o > 0; o >>= 1)
        acc += __shfl_down_sync(0xffffffffu, acc, o);
    __shared__ float wsum[8];
    if ((threadIdx.x & 31) == 0) wsum[threadIdx.x >> 5] = acc;
    __syncthreads();
    if (threadIdx.x == 0){
        float s = 0.0f;
        #pragma unroll
        for (int i = 0; i < 8; i++) s += wsum[i];
        atomicAdd(&g_stats[0], (double)s);
    }
}

__global__ void k_finalize(int N){
    double mean = g_stats[0] / (double)N;
    double chi0 = (double)g_chi[0] - mean;
    g_stats[1] = mean;
    g_stats[2] = 0.5 / fabs(chi0);
}

__global__ void k_writeout(float4* __restrict__ out){
    int i = blockIdx.x * 256 + threadIdx.x;   // over M3/4
    float mean = (float)g_stats[1];
    float sc   = (float)g_stats[2];
    float4 c = g_b_chi[i];
    out[i] = make_float4(sc*(c.x-mean), sc*(c.y-mean), sc*(c.z-mean), sc*(c.w-mean));
}

// ============================================================================
// launch
// ============================================================================
extern "C" void kernel_launch(void* const* d_in, const int* in_sizes, int n_in,
                              void* d_out, int out_size){
    const float* pts = (const float*)d_in[0];
    const float* nrm = (const float*)d_in[1];
    const int N = in_sizes[0] / 3;

    cudaFuncSetAttribute(k_plane_zy_fwd, cudaFuncAttributeMaxDynamicSharedMemorySize,
                         (int)PLANE_BYTES);
    cudaFuncSetAttribute(k_plane_yz_inv, cudaFuncAttributeMaxDynamicSharedMemorySize,
                         (int)PLANE_BYTES);

    k_init<<<1536, 1024>>>();
    k_scatter<<<(N + 255) / 256, 256>>>(pts, nrm, N);
    // forward: fused z+y per plane (both fields)
    k_plane_zy_fwd<<<dim3(128, 2), 1024, PLANE_BYTES>>>();
    // mirror-paired fused x-phase (kyA in [0,64])
    k_x_fused<<<dim3(8, 65), 256>>>();
    // inverse: fused kz+ky per plane, real output
    k_plane_yz_inv<<<128, 1024, PLANE_BYTES>>>();
    // gather, normalize, write
    k_interp<<<(N + 255) / 256, 256>>>(pts, N);
    k_finalize<<<1, 1>>>(N);
    k_writeout<<<2048, 256>>>((float4*)d_out);
}